// round 7
// baseline (speedup 1.0000x reference)
#include <cuda_runtime.h>
#include <cuda_bf16.h>

#define NN 100000
#define NE 1200000
#define NG 2048
#define DD 64

// Scratch (allocation-free, __device__ globals)
__device__ float g_h0[(size_t)NN * DD];
__device__ float g_h1[(size_t)NN * DD];
__device__ float g_h2[(size_t)NN * DD];
__device__ float g_poolcnt[(size_t)NG * DD + NG];   // pool | gcnt
__device__ int   g_degcur[2 * NN];                  // deg | cursor
__device__ int   g_off[NN];
__device__ int   g_elist[NE];

typedef unsigned long long u64;

// ---------- packed fp32 helpers ----------
__device__ __forceinline__ u64 pk2(float lo, float hi) {
    u64 r;
    asm("mov.b64 %0, {%1, %2};" : "=l"(r) : "f"(lo), "f"(hi));
    return r;
}
__device__ __forceinline__ void upk2(float& lo, float& hi, u64 v) {
    asm("mov.b64 {%0, %1}, %2;" : "=f"(lo), "=f"(hi) : "l"(v));
}
__device__ __forceinline__ void ffma2(u64& acc, u64 a, u64 b) {
    asm("fma.rn.f32x2 %0, %1, %2, %0;" : "+l"(acc) : "l"(a), "l"(b));
}
__device__ __forceinline__ void red_v4(float* p, float4 v) {
    asm volatile("red.global.add.v4.f32 [%0], {%1, %2, %3, %4};"
                 :: "l"(p), "f"(v.x), "f"(v.y), "f"(v.z), "f"(v.w) : "memory");
}

// ---------- h0[n] = emb[x[n]] ----------
__global__ void k_gather(const int* __restrict__ x, const float* __restrict__ emb,
                         float* __restrict__ h) {
    int t = blockIdx.x * blockDim.x + threadIdx.x;
    if (t >= NN * 16) return;
    int n = t >> 4, j = t & 15;
    const float4* e = (const float4*)(emb + (size_t)x[n] * DD);
    ((float4*)(h + (size_t)n * DD))[j] = e[j];
}

// ---------- deg[dst[e]] += 1 ----------
__global__ void k_deg(const int* __restrict__ dst, int* __restrict__ deg) {
    int e = blockIdx.x * blockDim.x + threadIdx.x;
    if (e < NE) atomicAdd(&deg[dst[e]], 1);
}

// ---------- single-block exclusive scan: off = exclusive_scan(deg) ----------
// 32 warps x 3136 contiguous elements each (98 coalesced 32-wide tiles/warp).
#define WCHUNK 3136   // 32*3136 = 100352 >= NN
__global__ __launch_bounds__(1024) void k_scan_one(const int* __restrict__ deg,
                                                   int* __restrict__ off) {
    __shared__ int wsum[32];
    int t = threadIdx.x, w = t >> 5, l = t & 31;
    int base = w * WCHUNK;
    int run = 0;
    // pass 1: provisional within-warp exclusive prefix
    for (int i = 0; i < 98; i++) {
        int n = base + i * 32 + l;
        int v = (n < NN) ? deg[n] : 0;
        int s = v;
        #pragma unroll
        for (int d = 1; d < 32; d <<= 1) {
            int x = __shfl_up_sync(0xffffffffu, s, d);
            if (l >= d) s += x;
        }
        if (n < NN) off[n] = run + (s - v);
        run += __shfl_sync(0xffffffffu, s, 31);
    }
    if (l == 0) wsum[w] = run;
    __syncthreads();
    if (w == 0) {
        int v = wsum[l];
        int s = v;
        #pragma unroll
        for (int d = 1; d < 32; d <<= 1) {
            int x = __shfl_up_sync(0xffffffffu, s, d);
            if (l >= d) s += x;
        }
        wsum[l] = s - v;   // exclusive warp base
    }
    __syncthreads();
    int wbase = wsum[w];
    if (wbase != 0) {
        for (int i = 0; i < 98; i++) {
            int n = base + i * 32 + l;
            if (n < NN) off[n] += wbase;
        }
    }
}

// ---------- CSR fill ----------
__global__ void k_fill(const int* __restrict__ src, const int* __restrict__ dst,
                       const int* __restrict__ off, int* __restrict__ cursor,
                       int* __restrict__ elist) {
    int e = blockIdx.x * blockDim.x + threadIdx.x;
    if (e >= NE) return;
    int d = dst[e];
    int p = atomicAdd(&cursor[d], 1);
    elist[off[d] + p] = src[e];
}

// ---------- fused neighbor-mean + dual GEMM + bias + relu ----------
// out[n] = relu( mean_{s in N(n)} h[s] @ Wl^T + bl + h[n] @ Wr^T )
// Tile: 64 nodes x 64 dims, 256 threads, 4x4 micro-tile, FFMA2.
// Aggregation: warp ww aggregates nodes ww*8..ww*8+7 (float2 per lane),
// writing the scaled mean transposed straight into sA rows 0..63.
#define SA_STRIDE 68
__global__ __launch_bounds__(256) void k_agglin(
    const float* __restrict__ h, const int* __restrict__ elist,
    const int* __restrict__ off, const int* __restrict__ deg,
    const float* __restrict__ Wl, const float* __restrict__ bl,
    const float* __restrict__ Wr, float* __restrict__ out)
{
    extern __shared__ float smem[];
    float* sW = smem;                 // [128][64]
    float* sA = smem + 128 * 64;      // [128][SA_STRIDE] swizzled
    const int tid  = threadIdx.x;
    const int ww   = tid >> 5;        // warp id 0..7
    const int lane = tid & 31;

    // Weights transposed: sW[k][d] = Wl[d][k]; sW[64+k][d] = Wr[d][k]
    for (int i = tid; i < 64 * 64; i += 256) {
        int d = i >> 6, k = i & 63;
        sW[k * 64 + d]        = Wl[i];
        sW[(64 + k) * 64 + d] = Wr[i];
    }

    const int q  = tid & 15;     // node quad
    const int dq = tid >> 4;     // dim quad
    const int d0 = dq * 4;
    float4 bias = *(const float4*)&bl[d0];
    __syncthreads();

    const float4* h4 = (const float4*)h;

    for (int n0 = blockIdx.x * 64; n0 < NN; n0 += gridDim.x * 64) {
        // Stage h^T (rows 64..127), 4 float4 per thread, swizzled cols
        for (int i = tid; i < 64 * 16; i += 256) {
            int m = i >> 4, kq = i & 15;
            int n = n0 + m;
            float4 vh = make_float4(0.f, 0.f, 0.f, 0.f);
            if (n < NN) vh = h4[(size_t)n * 16 + kq];
            int col = (((m >> 2) + kq) & 15) * 4 + (m & 3);
            int k = kq * 4;
            sA[(64 + k + 0) * SA_STRIDE + col] = vh.x;
            sA[(64 + k + 1) * SA_STRIDE + col] = vh.y;
            sA[(64 + k + 2) * SA_STRIDE + col] = vh.z;
            sA[(64 + k + 3) * SA_STRIDE + col] = vh.w;
        }

        // Aggregate neighbor means for 8 nodes per warp -> sA rows 0..63
        #pragma unroll 1
        for (int j = 0; j < 8; j++) {
            int m = ww * 8 + j;
            int n = n0 + m;
            float2 a0 = make_float2(0.f, 0.f), a1 = a0;
            int dg = 0;
            if (n < NN) {
                int beg = off[n];
                dg = deg[n];
                int i = beg, end = beg + dg;
                for (; i + 1 < end; i += 2) {
                    int s0 = elist[i], s1 = elist[i + 1];
                    float2 v0 = ((const float2*)(h + (size_t)s0 * DD))[lane];
                    float2 v1 = ((const float2*)(h + (size_t)s1 * DD))[lane];
                    a0.x += v0.x; a0.y += v0.y;
                    a1.x += v1.x; a1.y += v1.y;
                }
                if (i < end) {
                    int s0 = elist[i];
                    float2 v0 = ((const float2*)(h + (size_t)s0 * DD))[lane];
                    a0.x += v0.x; a0.y += v0.y;
                }
            }
            float inv = 1.0f / (float)max(dg, 1);
            float mx = (a0.x + a1.x) * inv;
            float my = (a0.y + a1.y) * inv;
            int k0 = 2 * lane;
            int col = (((m >> 2) + (k0 >> 2)) & 15) * 4 + (m & 3);
            sA[(k0 + 0) * SA_STRIDE + col] = mx;
            sA[(k0 + 1) * SA_STRIDE + col] = my;
        }
        __syncthreads();

        // GEMM: acc[node i][dim-pair j], f32x2 over dims (d0+2j, d0+2j+1)
        u64 acc[4][2];
        u64 b01 = pk2(bias.x, bias.y);
        u64 b23 = pk2(bias.z, bias.w);
        #pragma unroll
        for (int i = 0; i < 4; i++) { acc[i][0] = b01; acc[i][1] = b23; }

        #pragma unroll
        for (int kq = 0; kq < 32; kq++) {
            int col = ((q + kq) & 15) * 4;
            const float* ar = &sA[(kq * 4) * SA_STRIDE + col];
            #pragma unroll
            for (int c = 0; c < 4; c++) {
                int k = kq * 4 + c;
                float4 a = *(const float4*)(ar + c * SA_STRIDE);
                float4 w = *(const float4*)&sW[k * 64 + d0];
                u64 w01 = pk2(w.x, w.y);
                u64 w23 = pk2(w.z, w.w);
                u64 ax = pk2(a.x, a.x);
                u64 ay = pk2(a.y, a.y);
                u64 az = pk2(a.z, a.z);
                u64 aw = pk2(a.w, a.w);
                ffma2(acc[0][0], ax, w01); ffma2(acc[0][1], ax, w23);
                ffma2(acc[1][0], ay, w01); ffma2(acc[1][1], ay, w23);
                ffma2(acc[2][0], az, w01); ffma2(acc[2][1], az, w23);
                ffma2(acc[3][0], aw, w01); ffma2(acc[3][1], aw, w23);
            }
        }

        int m0 = q * 4;
        #pragma unroll
        for (int i = 0; i < 4; i++) {
            int n = n0 + m0 + i;
            if (n < NN) {
                float o0, o1, o2, o3;
                upk2(o0, o1, acc[i][0]);
                upk2(o2, o3, acc[i][1]);
                float4 o = make_float4(fmaxf(o0, 0.f), fmaxf(o1, 0.f),
                                       fmaxf(o2, 0.f), fmaxf(o3, 0.f));
                *(float4*)&out[(size_t)n * DD + d0] = o;
            }
        }
        __syncthreads();
    }
}

// ---------- global mean pool ----------
__global__ void k_pool(const float* __restrict__ h, const int* __restrict__ batch,
                       float* __restrict__ pool, float* __restrict__ gcnt) {
    int t = blockIdx.x * blockDim.x + threadIdx.x;
    if (t >= NN * 4) return;
    int n = t >> 2, j = t & 3;
    int g = batch[n];
    const float4* hr = (const float4*)(h + (size_t)n * DD) + j * 4;
    float* p = pool + (size_t)g * DD + (size_t)j * 16;
    #pragma unroll
    for (int i = 0; i < 4; i++) red_v4(p + i * 4, hr[i]);
    if (j == 0) atomicAdd(&gcnt[g], 1.0f);
}

// ---------- classifier ----------
__global__ void k_out(const float* __restrict__ pool, const float* __restrict__ gcnt,
                      const float* __restrict__ Wout, const float* __restrict__ bout,
                      float* __restrict__ out) {
    int t = blockIdx.x * blockDim.x + threadIdx.x;
    if (t >= NG * 2) return;
    int g = t >> 1, c = t & 1;
    float inv = 1.0f / fmaxf(gcnt[g], 1.0f);
    float acc = bout[c];
    const float* p = pool + (size_t)g * DD;
    const float* w = Wout + (size_t)c * DD;
    #pragma unroll
    for (int k = 0; k < DD; k++) acc += p[k] * inv * w[k];
    out[(size_t)g * 2 + c] = acc;
}

extern "C" void kernel_launch(void* const* d_in, const int* in_sizes, int n_in,
                              void* d_out, int out_size) {
    const int*   x     = (const int*)d_in[0];
    const int*   ei    = (const int*)d_in[1];
    const int*   src   = ei;          // edge_index[0]
    const int*   dst   = ei + NE;     // edge_index[1]
    const int*   batch = (const int*)d_in[2];
    const float* emb   = (const float*)d_in[3];
    const float* W1l   = (const float*)d_in[4];
    const float* b1l   = (const float*)d_in[5];
    const float* W1r   = (const float*)d_in[6];
    const float* W2l   = (const float*)d_in[7];
    const float* b2l   = (const float*)d_in[8];
    const float* W2r   = (const float*)d_in[9];
    const float* Wout  = (const float*)d_in[10];
    const float* bout  = (const float*)d_in[11];
    float* out = (float*)d_out;

    float *h0, *h1, *h2, *poolcnt;
    int *degcur, *off, *elist;
    cudaGetSymbolAddress((void**)&h0,      g_h0);
    cudaGetSymbolAddress((void**)&h1,      g_h1);
    cudaGetSymbolAddress((void**)&h2,      g_h2);
    cudaGetSymbolAddress((void**)&poolcnt, g_poolcnt);
    cudaGetSymbolAddress((void**)&degcur,  g_degcur);
    cudaGetSymbolAddress((void**)&off,     g_off);
    cudaGetSymbolAddress((void**)&elist,   g_elist);
    int*   deg    = degcur;
    int*   cursor = degcur + NN;
    float* pool   = poolcnt;
    float* gcnt   = poolcnt + (size_t)NG * DD;

    const int SMEM_LIN = (128 * 64 + 128 * SA_STRIDE) * 4;   // 67584 bytes
    cudaFuncSetAttribute(k_agglin, cudaFuncAttributeMaxDynamicSharedMemorySize, SMEM_LIN);

    const int T = 256;

    // CSR build
    cudaMemsetAsync(degcur, 0, 2 * NN * sizeof(int));
    k_gather<<<(NN * 16 + T - 1) / T, T>>>(x, emb, h0);
    k_deg<<<(NE + T - 1) / T, T>>>(dst, deg);
    k_scan_one<<<1, 1024>>>(deg, off);
    k_fill<<<(NE + T - 1) / T, T>>>(src, dst, off, cursor, elist);

    // Layer 1 + Layer 2 (fused agg + linear)
    k_agglin<<<444, 256, SMEM_LIN>>>(h0, elist, off, deg, W1l, b1l, W1r, h1);
    k_agglin<<<444, 256, SMEM_LIN>>>(h1, elist, off, deg, W2l, b2l, W2r, h2);

    // Pool + classify
    cudaMemsetAsync(poolcnt, 0, ((size_t)NG * DD + NG) * sizeof(float));
    k_pool<<<(NN * 4 + T - 1) / T, T>>>(h2, batch, pool, gcnt);
    k_out<<<(NG * 2 + 127) / 128, 128>>>(pool, gcnt, Wout, bout, out);
}

// round 8
// speedup vs baseline: 1.1091x; 1.1091x over previous
#include <cuda_runtime.h>
#include <cuda_bf16.h>

#define NN 100000
#define NE 1200000
#define NG 2048
#define DD 64

// Scratch (allocation-free, __device__ globals)
__device__ float g_h0[(size_t)NN * DD];
__device__ float g_h1[(size_t)NN * DD];
__device__ float g_h2[(size_t)NN * DD];
__device__ float g_agg[(size_t)NN * DD];            // mean buffer
__device__ float g_poolcnt[(size_t)NG * DD + NG];   // pool | gcnt
__device__ int   g_degcur[2 * NN];                  // deg | cursor
__device__ int   g_off[NN];
__device__ int   g_elist[NE];

typedef unsigned long long u64;

// ---------- packed fp32 helpers ----------
__device__ __forceinline__ u64 pk2(float lo, float hi) {
    u64 r;
    asm("mov.b64 %0, {%1, %2};" : "=l"(r) : "f"(lo), "f"(hi));
    return r;
}
__device__ __forceinline__ void upk2(float& lo, float& hi, u64 v) {
    asm("mov.b64 {%0, %1}, %2;" : "=f"(lo), "=f"(hi) : "l"(v));
}
__device__ __forceinline__ void ffma2(u64& acc, u64 a, u64 b) {
    asm("fma.rn.f32x2 %0, %1, %2, %0;" : "+l"(acc) : "l"(a), "l"(b));
}
__device__ __forceinline__ void red_v4(float* p, float4 v) {
    asm volatile("red.global.add.v4.f32 [%0], {%1, %2, %3, %4};"
                 :: "l"(p), "f"(v.x), "f"(v.y), "f"(v.z), "f"(v.w) : "memory");
}

// ---------- h0[n] = emb[x[n]] ----------
__global__ void k_gather(const int* __restrict__ x, const float* __restrict__ emb,
                         float* __restrict__ h) {
    int t = blockIdx.x * blockDim.x + threadIdx.x;
    if (t >= NN * 16) return;
    int n = t >> 4, j = t & 15;
    const float4* e = (const float4*)(emb + (size_t)x[n] * DD);
    ((float4*)(h + (size_t)n * DD))[j] = e[j];
}

// ---------- deg[dst[e]] += 1 ----------
__global__ void k_deg(const int* __restrict__ dst, int* __restrict__ deg) {
    int e = blockIdx.x * blockDim.x + threadIdx.x;
    if (e < NE) atomicAdd(&deg[dst[e]], 1);
}

// ---------- single-block exclusive scan: off = exclusive_scan(deg) ----------
// 32 warps x 3136 contiguous elements each (98 coalesced 32-wide tiles/warp).
#define WCHUNK 3136   // 32*3136 = 100352 >= NN
__global__ __launch_bounds__(1024) void k_scan_one(const int* __restrict__ deg,
                                                   int* __restrict__ off) {
    __shared__ int wsum[32];
    int t = threadIdx.x, w = t >> 5, l = t & 31;
    int base = w * WCHUNK;
    int run = 0;
    for (int i = 0; i < 98; i++) {
        int n = base + i * 32 + l;
        int v = (n < NN) ? deg[n] : 0;
        int s = v;
        #pragma unroll
        for (int d = 1; d < 32; d <<= 1) {
            int x = __shfl_up_sync(0xffffffffu, s, d);
            if (l >= d) s += x;
        }
        if (n < NN) off[n] = run + (s - v);
        run += __shfl_sync(0xffffffffu, s, 31);
    }
    if (l == 0) wsum[w] = run;
    __syncthreads();
    if (w == 0) {
        int v = wsum[l];
        int s = v;
        #pragma unroll
        for (int d = 1; d < 32; d <<= 1) {
            int x = __shfl_up_sync(0xffffffffu, s, d);
            if (l >= d) s += x;
        }
        wsum[l] = s - v;   // exclusive warp base
    }
    __syncthreads();
    int wbase = wsum[w];
    if (wbase != 0) {
        for (int i = 0; i < 98; i++) {
            int n = base + i * 32 + l;
            if (n < NN) off[n] += wbase;
        }
    }
}

// ---------- CSR fill ----------
__global__ void k_fill(const int* __restrict__ src, const int* __restrict__ dst,
                       const int* __restrict__ off, int* __restrict__ cursor,
                       int* __restrict__ elist) {
    int e = blockIdx.x * blockDim.x + threadIdx.x;
    if (e >= NE) return;
    int d = dst[e];
    int p = atomicAdd(&cursor[d], 1);
    elist[off[d] + p] = src[e];
}

// ---------- mean aggregation: one warp per node, unroll 2 (R4-measured) ----------
__global__ __launch_bounds__(256) void k_aggmean(
    const float* __restrict__ h, const int* __restrict__ elist,
    const int* __restrict__ off, const int* __restrict__ deg,
    float* __restrict__ mean) {
    int w = (blockIdx.x * blockDim.x + threadIdx.x) >> 5;
    int lane = threadIdx.x & 31;
    if (w >= NN) return;
    int beg = off[w], dg = deg[w];
    float2 a0 = make_float2(0.f, 0.f), a1 = a0;
    int i = beg, end = beg + dg;
    for (; i + 1 < end; i += 2) {
        int s0 = elist[i], s1 = elist[i + 1];
        float2 v0 = ((const float2*)(h + (size_t)s0 * DD))[lane];
        float2 v1 = ((const float2*)(h + (size_t)s1 * DD))[lane];
        a0.x += v0.x; a0.y += v0.y;
        a1.x += v1.x; a1.y += v1.y;
    }
    if (i < end) {
        int s0 = elist[i];
        float2 v0 = ((const float2*)(h + (size_t)s0 * DD))[lane];
        a0.x += v0.x; a0.y += v0.y;
    }
    float inv = 1.0f / (float)max(dg, 1);
    float2 o = make_float2((a0.x + a1.x) * inv, (a0.y + a1.y) * inv);
    ((float2*)(mean + (size_t)w * DD))[lane] = o;
}

// ---------- fused dual GEMM + bias + relu (R4 version — measured best) ----------
// out[n] = relu( mean[n] @ Wl^T + bl + h[n] @ Wr^T )
// 64 nodes x 64 dims per block, 256 threads, 4x4 micro-tile, FFMA2 (fma.rn.f32x2).
#define SA_STRIDE 68
__global__ __launch_bounds__(256) void k_linear(
    const float* __restrict__ mean, const float* __restrict__ h,
    const float* __restrict__ Wl, const float* __restrict__ bl,
    const float* __restrict__ Wr, float* __restrict__ out)
{
    extern __shared__ float smem[];
    float* sW = smem;                 // [128][64]
    float* sA = smem + 128 * 64;      // [128][SA_STRIDE] swizzled
    const int tid = threadIdx.x;

    // Weights transposed: sW[k][d] = Wl[d][k]; sW[64+k][d] = Wr[d][k]
    for (int i = tid; i < 64 * 64; i += 256) {
        int d = i >> 6, k = i & 63;
        sW[k * 64 + d]        = Wl[i];
        sW[(64 + k) * 64 + d] = Wr[i];
    }

    const int q  = tid & 15;     // node quad
    const int dq = tid >> 4;     // dim quad
    const int d0 = dq * 4;
    float4 bias = *(const float4*)&bl[d0];
    __syncthreads();

    const float4* m4 = (const float4*)mean;
    const float4* h4 = (const float4*)h;

    for (int n0 = blockIdx.x * 64; n0 < NN; n0 += gridDim.x * 64) {
        // Stage A^T swizzled: rows 0..63 = mean^T, 64..127 = h^T
        for (int i = tid; i < 64 * 16; i += 256) {
            int m = i >> 4, kq = i & 15;
            int n = n0 + m;
            float4 va = make_float4(0.f, 0.f, 0.f, 0.f), vh = va;
            if (n < NN) {
                va = m4[(size_t)n * 16 + kq];
                vh = h4[(size_t)n * 16 + kq];
            }
            int mb = m >> 2, mw = m & 3;
            int col = ((mb + kq) & 15) * 4 + mw;
            int k = kq * 4;
            sA[(k + 0) * SA_STRIDE + col] = va.x;
            sA[(k + 1) * SA_STRIDE + col] = va.y;
            sA[(k + 2) * SA_STRIDE + col] = va.z;
            sA[(k + 3) * SA_STRIDE + col] = va.w;
            sA[(64 + k + 0) * SA_STRIDE + col] = vh.x;
            sA[(64 + k + 1) * SA_STRIDE + col] = vh.y;
            sA[(64 + k + 2) * SA_STRIDE + col] = vh.z;
            sA[(64 + k + 3) * SA_STRIDE + col] = vh.w;
        }
        __syncthreads();

        // acc[node i][dim-pair j] : f32x2 over dims (d0+2j, d0+2j+1)
        u64 acc[4][2];
        u64 b01 = pk2(bias.x, bias.y);
        u64 b23 = pk2(bias.z, bias.w);
        #pragma unroll
        for (int i = 0; i < 4; i++) { acc[i][0] = b01; acc[i][1] = b23; }

        #pragma unroll
        for (int kq = 0; kq < 32; kq++) {
            int col = ((q + kq) & 15) * 4;
            const float* ar = &sA[(kq * 4) * SA_STRIDE + col];
            #pragma unroll
            for (int c = 0; c < 4; c++) {
                int k = kq * 4 + c;
                float4 a = *(const float4*)(ar + c * SA_STRIDE);
                float4 w = *(const float4*)&sW[k * 64 + d0];
                u64 w01 = pk2(w.x, w.y);
                u64 w23 = pk2(w.z, w.w);
                u64 ax = pk2(a.x, a.x);
                u64 ay = pk2(a.y, a.y);
                u64 az = pk2(a.z, a.z);
                u64 aw = pk2(a.w, a.w);
                ffma2(acc[0][0], ax, w01); ffma2(acc[0][1], ax, w23);
                ffma2(acc[1][0], ay, w01); ffma2(acc[1][1], ay, w23);
                ffma2(acc[2][0], az, w01); ffma2(acc[2][1], az, w23);
                ffma2(acc[3][0], aw, w01); ffma2(acc[3][1], aw, w23);
            }
        }

        int m0 = q * 4;
        #pragma unroll
        for (int i = 0; i < 4; i++) {
            int n = n0 + m0 + i;
            if (n < NN) {
                float o0, o1, o2, o3;
                upk2(o0, o1, acc[i][0]);
                upk2(o2, o3, acc[i][1]);
                float4 o = make_float4(fmaxf(o0, 0.f), fmaxf(o1, 0.f),
                                       fmaxf(o2, 0.f), fmaxf(o3, 0.f));
                *(float4*)&out[(size_t)n * DD + d0] = o;
            }
        }
        __syncthreads();
    }
}

// ---------- global mean pool ----------
__global__ void k_pool(const float* __restrict__ h, const int* __restrict__ batch,
                       float* __restrict__ pool, float* __restrict__ gcnt) {
    int t = blockIdx.x * blockDim.x + threadIdx.x;
    if (t >= NN * 4) return;
    int n = t >> 2, j = t & 3;
    int g = batch[n];
    const float4* hr = (const float4*)(h + (size_t)n * DD) + j * 4;
    float* p = pool + (size_t)g * DD + (size_t)j * 16;
    #pragma unroll
    for (int i = 0; i < 4; i++) red_v4(p + i * 4, hr[i]);
    if (j == 0) atomicAdd(&gcnt[g], 1.0f);
}

// ---------- classifier ----------
__global__ void k_out(const float* __restrict__ pool, const float* __restrict__ gcnt,
                      const float* __restrict__ Wout, const float* __restrict__ bout,
                      float* __restrict__ out) {
    int t = blockIdx.x * blockDim.x + threadIdx.x;
    if (t >= NG * 2) return;
    int g = t >> 1, c = t & 1;
    float inv = 1.0f / fmaxf(gcnt[g], 1.0f);
    float acc = bout[c];
    const float* p = pool + (size_t)g * DD;
    const float* w = Wout + (size_t)c * DD;
    #pragma unroll
    for (int k = 0; k < DD; k++) acc += p[k] * inv * w[k];
    out[(size_t)g * 2 + c] = acc;
}

extern "C" void kernel_launch(void* const* d_in, const int* in_sizes, int n_in,
                              void* d_out, int out_size) {
    const int*   x     = (const int*)d_in[0];
    const int*   ei    = (const int*)d_in[1];
    const int*   src   = ei;          // edge_index[0]
    const int*   dst   = ei + NE;     // edge_index[1]
    const int*   batch = (const int*)d_in[2];
    const float* emb   = (const float*)d_in[3];
    const float* W1l   = (const float*)d_in[4];
    const float* b1l   = (const float*)d_in[5];
    const float* W1r   = (const float*)d_in[6];
    const float* W2l   = (const float*)d_in[7];
    const float* b2l   = (const float*)d_in[8];
    const float* W2r   = (const float*)d_in[9];
    const float* Wout  = (const float*)d_in[10];
    const float* bout  = (const float*)d_in[11];
    float* out = (float*)d_out;

    float *h0, *h1, *h2, *mean, *poolcnt;
    int *degcur, *off, *elist;
    cudaGetSymbolAddress((void**)&h0,      g_h0);
    cudaGetSymbolAddress((void**)&h1,      g_h1);
    cudaGetSymbolAddress((void**)&h2,      g_h2);
    cudaGetSymbolAddress((void**)&mean,    g_agg);
    cudaGetSymbolAddress((void**)&poolcnt, g_poolcnt);
    cudaGetSymbolAddress((void**)&degcur,  g_degcur);
    cudaGetSymbolAddress((void**)&off,     g_off);
    cudaGetSymbolAddress((void**)&elist,   g_elist);
    int*   deg    = degcur;
    int*   cursor = degcur + NN;
    float* pool   = poolcnt;
    float* gcnt   = poolcnt + (size_t)NG * DD;

    const int SMEM_LIN = (128 * 64 + 128 * SA_STRIDE) * 4;   // 67584 bytes
    cudaFuncSetAttribute(k_linear, cudaFuncAttributeMaxDynamicSharedMemorySize, SMEM_LIN);

    const int T = 256;

    // CSR build (reused by both layers)
    cudaMemsetAsync(degcur, 0, 2 * NN * sizeof(int));
    k_gather<<<(NN * 16 + T - 1) / T, T>>>(x, emb, h0);
    k_deg<<<(NE + T - 1) / T, T>>>(dst, deg);
    k_scan_one<<<1, 1024>>>(deg, off);
    k_fill<<<(NE + T - 1) / T, T>>>(src, dst, off, cursor, elist);

    // Layer 1   (aggmean is 6th captured node -> ncu -s 5 profiles it)
    k_aggmean<<<(NN * 32 + T - 1) / T, T>>>(h0, elist, off, deg, mean);
    k_linear<<<444, 256, SMEM_LIN>>>(mean, h0, W1l, b1l, W1r, h1);

    // Layer 2
    k_aggmean<<<(NN * 32 + T - 1) / T, T>>>(h1, elist, off, deg, mean);
    k_linear<<<444, 256, SMEM_LIN>>>(mean, h1, W2l, b2l, W2r, h2);

    // Pool + classify
    cudaMemsetAsync(poolcnt, 0, ((size_t)NG * DD + NG) * sizeof(float));
    k_pool<<<(NN * 4 + T - 1) / T, T>>>(h2, batch, pool, gcnt);
    k_out<<<(NG * 2 + 127) / 128, 128>>>(pool, gcnt, Wout, bout, out);
}

// round 9
// speedup vs baseline: 1.2034x; 1.0850x over previous
#include <cuda_runtime.h>
#include <cuda_bf16.h>
#include <cuda_fp16.h>
#include <cub/cub.cuh>

#define NN 100000
#define NE 1200000
#define NG 2048
#define DD 64

// Scratch (allocation-free, __device__ globals)
__device__ float  g_h0[(size_t)NN * DD];
__device__ float  g_h1[(size_t)NN * DD];
__device__ float  g_h2[(size_t)NN * DD];
__device__ __half g_hh[(size_t)NN * DD];             // fp16 mirror for gathers
__device__ float  g_agg[(size_t)NN * DD];            // mean buffer
__device__ float  g_poolcnt[(size_t)NG * DD + NG];   // pool | gcnt
__device__ int    g_degcur[2 * NN];                  // deg | cursor
__device__ int    g_off[NN];
__device__ int    g_elist[NE];
__device__ unsigned char g_cubtmp[1 << 20];          // cub scan temp (~KBs needed)

typedef unsigned long long u64;

// ---------- packed fp32 helpers ----------
__device__ __forceinline__ u64 pk2(float lo, float hi) {
    u64 r;
    asm("mov.b64 %0, {%1, %2};" : "=l"(r) : "f"(lo), "f"(hi));
    return r;
}
__device__ __forceinline__ void upk2(float& lo, float& hi, u64 v) {
    asm("mov.b64 {%0, %1}, %2;" : "=f"(lo), "=f"(hi) : "l"(v));
}
__device__ __forceinline__ void ffma2(u64& acc, u64 a, u64 b) {
    asm("fma.rn.f32x2 %0, %1, %2, %0;" : "+l"(acc) : "l"(a), "l"(b));
}
__device__ __forceinline__ void red_v4(float* p, float4 v) {
    asm volatile("red.global.add.v4.f32 [%0], {%1, %2, %3, %4};"
                 :: "l"(p), "f"(v.x), "f"(v.y), "f"(v.z), "f"(v.w) : "memory");
}

// ---------- h0[n] = emb[x[n]]  (fp32 + fp16 mirror) ----------
__global__ void k_gather(const int* __restrict__ x, const float* __restrict__ emb,
                         float* __restrict__ h, __half* __restrict__ hh) {
    int t = blockIdx.x * blockDim.x + threadIdx.x;
    if (t >= NN * 16) return;
    int n = t >> 4, j = t & 15;
    float4 v = ((const float4*)(emb + (size_t)x[n] * DD))[j];
    ((float4*)(h + (size_t)n * DD))[j] = v;
    __half2* hp = (__half2*)(hh + (size_t)n * DD) + j * 2;
    hp[0] = __floats2half2_rn(v.x, v.y);
    hp[1] = __floats2half2_rn(v.z, v.w);
}

// ---------- deg[dst[e]] += 1 ----------
__global__ void k_deg(const int* __restrict__ dst, int* __restrict__ deg) {
    int e = blockIdx.x * blockDim.x + threadIdx.x;
    if (e < NE) atomicAdd(&deg[dst[e]], 1);
}

// ---------- CSR fill ----------
__global__ void k_fill(const int* __restrict__ src, const int* __restrict__ dst,
                       const int* __restrict__ off, int* __restrict__ cursor,
                       int* __restrict__ elist) {
    int e = blockIdx.x * blockDim.x + threadIdx.x;
    if (e >= NE) return;
    int d = dst[e];
    int p = atomicAdd(&cursor[d], 1);
    elist[off[d] + p] = src[e];
}

// ---------- mean aggregation: one warp per node, fp16 gather, fp32 accum ----------
__global__ __launch_bounds__(256) void k_aggmean(
    const __half* __restrict__ hh, const int* __restrict__ elist,
    const int* __restrict__ off, const int* __restrict__ deg,
    float* __restrict__ mean) {
    int w = (blockIdx.x * blockDim.x + threadIdx.x) >> 5;
    int lane = threadIdx.x & 31;
    if (w >= NN) return;
    int beg = off[w], dg = deg[w];
    float2 a0 = make_float2(0.f, 0.f), a1 = a0;
    int i = beg, end = beg + dg;
    for (; i + 1 < end; i += 2) {
        int s0 = elist[i], s1 = elist[i + 1];
        float2 v0 = __half22float2(((const __half2*)(hh + (size_t)s0 * DD))[lane]);
        float2 v1 = __half22float2(((const __half2*)(hh + (size_t)s1 * DD))[lane]);
        a0.x += v0.x; a0.y += v0.y;
        a1.x += v1.x; a1.y += v1.y;
    }
    if (i < end) {
        int s0 = elist[i];
        float2 v0 = __half22float2(((const __half2*)(hh + (size_t)s0 * DD))[lane]);
        a0.x += v0.x; a0.y += v0.y;
    }
    float inv = 1.0f / (float)max(dg, 1);
    float2 o = make_float2((a0.x + a1.x) * inv, (a0.y + a1.y) * inv);
    ((float2*)(mean + (size_t)w * DD))[lane] = o;
}

// ---------- fused dual GEMM + bias + relu (R4 core) + fp16 mirror write ----------
// out[n] = relu( mean[n] @ Wl^T + bl + h[n] @ Wr^T )
// 64 nodes x 64 dims per block, 256 threads, 4x4 micro-tile, FFMA2 (fma.rn.f32x2).
#define SA_STRIDE 68
__global__ __launch_bounds__(256) void k_linear(
    const float* __restrict__ mean, const float* __restrict__ h,
    const float* __restrict__ Wl, const float* __restrict__ bl,
    const float* __restrict__ Wr, float* __restrict__ out,
    __half* __restrict__ outh)
{
    extern __shared__ float smem[];
    float* sW = smem;                 // [128][64]
    float* sA = smem + 128 * 64;      // [128][SA_STRIDE] swizzled
    const int tid = threadIdx.x;

    // Weights transposed: sW[k][d] = Wl[d][k]; sW[64+k][d] = Wr[d][k]
    for (int i = tid; i < 64 * 64; i += 256) {
        int d = i >> 6, k = i & 63;
        sW[k * 64 + d]        = Wl[i];
        sW[(64 + k) * 64 + d] = Wr[i];
    }

    const int q  = tid & 15;     // node quad
    const int dq = tid >> 4;     // dim quad
    const int d0 = dq * 4;
    float4 bias = *(const float4*)&bl[d0];
    __syncthreads();

    const float4* m4 = (const float4*)mean;
    const float4* h4 = (const float4*)h;

    for (int n0 = blockIdx.x * 64; n0 < NN; n0 += gridDim.x * 64) {
        // Stage A^T swizzled: rows 0..63 = mean^T, 64..127 = h^T
        for (int i = tid; i < 64 * 16; i += 256) {
            int m = i >> 4, kq = i & 15;
            int n = n0 + m;
            float4 va = make_float4(0.f, 0.f, 0.f, 0.f), vh = va;
            if (n < NN) {
                va = m4[(size_t)n * 16 + kq];
                vh = h4[(size_t)n * 16 + kq];
            }
            int mb = m >> 2, mw = m & 3;
            int col = ((mb + kq) & 15) * 4 + mw;
            int k = kq * 4;
            sA[(k + 0) * SA_STRIDE + col] = va.x;
            sA[(k + 1) * SA_STRIDE + col] = va.y;
            sA[(k + 2) * SA_STRIDE + col] = va.z;
            sA[(k + 3) * SA_STRIDE + col] = va.w;
            sA[(64 + k + 0) * SA_STRIDE + col] = vh.x;
            sA[(64 + k + 1) * SA_STRIDE + col] = vh.y;
            sA[(64 + k + 2) * SA_STRIDE + col] = vh.z;
            sA[(64 + k + 3) * SA_STRIDE + col] = vh.w;
        }
        __syncthreads();

        // acc[node i][dim-pair j] : f32x2 over dims (d0+2j, d0+2j+1)
        u64 acc[4][2];
        u64 b01 = pk2(bias.x, bias.y);
        u64 b23 = pk2(bias.z, bias.w);
        #pragma unroll
        for (int i = 0; i < 4; i++) { acc[i][0] = b01; acc[i][1] = b23; }

        #pragma unroll
        for (int kq = 0; kq < 32; kq++) {
            int col = ((q + kq) & 15) * 4;
            const float* ar = &sA[(kq * 4) * SA_STRIDE + col];
            #pragma unroll
            for (int c = 0; c < 4; c++) {
                int k = kq * 4 + c;
                float4 a = *(const float4*)(ar + c * SA_STRIDE);
                float4 w = *(const float4*)&sW[k * 64 + d0];
                u64 w01 = pk2(w.x, w.y);
                u64 w23 = pk2(w.z, w.w);
                u64 ax = pk2(a.x, a.x);
                u64 ay = pk2(a.y, a.y);
                u64 az = pk2(a.z, a.z);
                u64 aw = pk2(a.w, a.w);
                ffma2(acc[0][0], ax, w01); ffma2(acc[0][1], ax, w23);
                ffma2(acc[1][0], ay, w01); ffma2(acc[1][1], ay, w23);
                ffma2(acc[2][0], az, w01); ffma2(acc[2][1], az, w23);
                ffma2(acc[3][0], aw, w01); ffma2(acc[3][1], aw, w23);
            }
        }

        int m0 = q * 4;
        #pragma unroll
        for (int i = 0; i < 4; i++) {
            int n = n0 + m0 + i;
            if (n < NN) {
                float o0, o1, o2, o3;
                upk2(o0, o1, acc[i][0]);
                upk2(o2, o3, acc[i][1]);
                float4 o = make_float4(fmaxf(o0, 0.f), fmaxf(o1, 0.f),
                                       fmaxf(o2, 0.f), fmaxf(o3, 0.f));
                *(float4*)&out[(size_t)n * DD + d0] = o;
                __half2* hp = (__half2*)(outh + (size_t)n * DD + d0);
                hp[0] = __floats2half2_rn(o.x, o.y);
                hp[1] = __floats2half2_rn(o.z, o.w);
            }
        }
        __syncthreads();
    }
}

// ---------- global mean pool ----------
__global__ void k_pool(const float* __restrict__ h, const int* __restrict__ batch,
                       float* __restrict__ pool, float* __restrict__ gcnt) {
    int t = blockIdx.x * blockDim.x + threadIdx.x;
    if (t >= NN * 4) return;
    int n = t >> 2, j = t & 3;
    int g = batch[n];
    const float4* hr = (const float4*)(h + (size_t)n * DD) + j * 4;
    float* p = pool + (size_t)g * DD + (size_t)j * 16;
    #pragma unroll
    for (int i = 0; i < 4; i++) red_v4(p + i * 4, hr[i]);
    if (j == 0) atomicAdd(&gcnt[g], 1.0f);
}

// ---------- classifier ----------
__global__ void k_out(const float* __restrict__ pool, const float* __restrict__ gcnt,
                      const float* __restrict__ Wout, const float* __restrict__ bout,
                      float* __restrict__ out) {
    int t = blockIdx.x * blockDim.x + threadIdx.x;
    if (t >= NG * 2) return;
    int g = t >> 1, c = t & 1;
    float inv = 1.0f / fmaxf(gcnt[g], 1.0f);
    float acc = bout[c];
    const float* p = pool + (size_t)g * DD;
    const float* w = Wout + (size_t)c * DD;
    #pragma unroll
    for (int k = 0; k < DD; k++) acc += p[k] * inv * w[k];
    out[(size_t)g * 2 + c] = acc;
}

extern "C" void kernel_launch(void* const* d_in, const int* in_sizes, int n_in,
                              void* d_out, int out_size) {
    const int*   x     = (const int*)d_in[0];
    const int*   ei    = (const int*)d_in[1];
    const int*   src   = ei;          // edge_index[0]
    const int*   dst   = ei + NE;     // edge_index[1]
    const int*   batch = (const int*)d_in[2];
    const float* emb   = (const float*)d_in[3];
    const float* W1l   = (const float*)d_in[4];
    const float* b1l   = (const float*)d_in[5];
    const float* W1r   = (const float*)d_in[6];
    const float* W2l   = (const float*)d_in[7];
    const float* b2l   = (const float*)d_in[8];
    const float* W2r   = (const float*)d_in[9];
    const float* Wout  = (const float*)d_in[10];
    const float* bout  = (const float*)d_in[11];
    float* out = (float*)d_out;

    float *h0, *h1, *h2, *mean, *poolcnt;
    __half* hh;
    int *degcur, *off, *elist;
    unsigned char* cubtmp;
    cudaGetSymbolAddress((void**)&h0,      g_h0);
    cudaGetSymbolAddress((void**)&h1,      g_h1);
    cudaGetSymbolAddress((void**)&h2,      g_h2);
    cudaGetSymbolAddress((void**)&hh,      g_hh);
    cudaGetSymbolAddress((void**)&mean,    g_agg);
    cudaGetSymbolAddress((void**)&poolcnt, g_poolcnt);
    cudaGetSymbolAddress((void**)&degcur,  g_degcur);
    cudaGetSymbolAddress((void**)&off,     g_off);
    cudaGetSymbolAddress((void**)&elist,   g_elist);
    cudaGetSymbolAddress((void**)&cubtmp,  g_cubtmp);
    int*   deg    = degcur;
    int*   cursor = degcur + NN;
    float* pool   = poolcnt;
    float* gcnt   = poolcnt + (size_t)NG * DD;

    const int SMEM_LIN = (128 * 64 + 128 * SA_STRIDE) * 4;   // 67584 bytes
    cudaFuncSetAttribute(k_linear, cudaFuncAttributeMaxDynamicSharedMemorySize, SMEM_LIN);

    const int T = 256;

    // CSR build (reused by both layers)
    cudaMemsetAsync(degcur, 0, 2 * NN * sizeof(int));
    k_gather<<<(NN * 16 + T - 1) / T, T>>>(x, emb, h0, hh);
    k_deg<<<(NE + T - 1) / T, T>>>(dst, deg);
    {
        size_t tmp_bytes = sizeof(g_cubtmp);
        cub::DeviceScan::ExclusiveSum((void*)cubtmp, tmp_bytes, deg, off, NN);
    }
    k_fill<<<(NE + T - 1) / T, T>>>(src, dst, off, cursor, elist);

    // Layer 1  (fp16 gather; k_linear writes h1 fp32 + fp16 mirror)
    k_aggmean<<<(NN * 32 + T - 1) / T, T>>>(hh, elist, off, deg, mean);
    k_linear<<<444, 256, SMEM_LIN>>>(mean, h0, W1l, b1l, W1r, h1, hh);

    // Layer 2
    k_aggmean<<<(NN * 32 + T - 1) / T, T>>>(hh, elist, off, deg, mean);
    k_linear<<<444, 256, SMEM_LIN>>>(mean, h1, W2l, b2l, W2r, h2, hh);

    // Pool + classify
    cudaMemsetAsync(poolcnt, 0, ((size_t)NG * DD + NG) * sizeof(float));
    k_pool<<<(NN * 4 + T - 1) / T, T>>>(h2, batch, pool, gcnt);
    k_out<<<(NG * 2 + 127) / 128, 128>>>(pool, gcnt, Wout, bout, out);
}

// round 10
// speedup vs baseline: 1.2152x; 1.0098x over previous
#include <cuda_runtime.h>
#include <cuda_bf16.h>

#define NN 100000
#define NE 1200000
#define NG 2048
#define DD 64
#define SCAN_B 1024
#define SCAN_NB 98   // 98*1024 = 100352 >= NN

// Scratch (allocation-free, __device__ globals)
__device__ float g_h0[(size_t)NN * DD];
__device__ float g_h1[(size_t)NN * DD];
__device__ float g_h2[(size_t)NN * DD];
__device__ float g_agg[(size_t)NN * DD];      // mean buffer
__device__ float g_pool[(size_t)NG * DD];
__device__ float g_gcnt[NG];
__device__ int   g_deg[NN];
__device__ int   g_off[NN];
__device__ int   g_rank[NE];                  // edge rank within its dst
__device__ int   g_elist[NE];
__device__ int   g_bsum[SCAN_NB];
__device__ int   g_bpre[SCAN_NB];

typedef unsigned long long u64;

// ---------- packed fp32 helpers ----------
__device__ __forceinline__ u64 pk2(float lo, float hi) {
    u64 r;
    asm("mov.b64 %0, {%1, %2};" : "=l"(r) : "f"(lo), "f"(hi));
    return r;
}
__device__ __forceinline__ void upk2(float& lo, float& hi, u64 v) {
    asm("mov.b64 {%0, %1}, %2;" : "=f"(lo), "=f"(hi) : "l"(v));
}
__device__ __forceinline__ void ffma2(u64& acc, u64 a, u64 b) {
    asm("fma.rn.f32x2 %0, %1, %2, %0;" : "+l"(acc) : "l"(a), "l"(b));
}
__device__ __forceinline__ void red_v4(float* p, float4 v) {
    asm volatile("red.global.add.v4.f32 [%0], {%1, %2, %3, %4};"
                 :: "l"(p), "f"(v.x), "f"(v.y), "f"(v.z), "f"(v.w) : "memory");
}

// ---------- h0[n] = emb[x[n]] ----------
__global__ void k_gather(const int* __restrict__ x, const float* __restrict__ emb,
                         float* __restrict__ h) {
    int t = blockIdx.x * blockDim.x + threadIdx.x;
    if (t >= NN * 16) return;
    int n = t >> 4, j = t & 15;
    const float4* e = (const float4*)(emb + (size_t)x[n] * DD);
    ((float4*)(h + (size_t)n * DD))[j] = e[j];
}

// ---------- deg[dst[e]] += 1, saving each edge's rank ----------
__global__ void k_degrank(const int* __restrict__ dst, int* __restrict__ deg,
                          int* __restrict__ rank) {
    int e = blockIdx.x * blockDim.x + threadIdx.x;
    if (e < NE) rank[e] = atomicAdd(&deg[dst[e]], 1);
}

// ---------- CSR scan (3-kernel, R4-measured) ----------
__global__ void k_scan_part(const int* __restrict__ deg, int* __restrict__ bsum) {
    __shared__ int s[SCAN_B];
    int t = threadIdx.x, n = blockIdx.x * SCAN_B + t;
    s[t] = (n < NN) ? deg[n] : 0;
    __syncthreads();
    for (int d = SCAN_B / 2; d > 0; d >>= 1) {
        if (t < d) s[t] += s[t + d];
        __syncthreads();
    }
    if (t == 0) bsum[blockIdx.x] = s[0];
}

__global__ void k_scan_mid(const int* __restrict__ bsum, int* __restrict__ bpre) {
    __shared__ int s[128];
    int t = threadIdx.x;
    int v = (t < SCAN_NB) ? bsum[t] : 0;
    s[t] = v;
    __syncthreads();
    for (int d = 1; d < 128; d <<= 1) {
        int x = (t >= d) ? s[t - d] : 0;
        __syncthreads();
        s[t] += x;
        __syncthreads();
    }
    if (t < SCAN_NB) bpre[t] = s[t] - v;   // exclusive
}

__global__ void k_scan_add(const int* __restrict__ deg, const int* __restrict__ bpre,
                           int* __restrict__ off) {
    __shared__ int s[SCAN_B];
    int t = threadIdx.x, n = blockIdx.x * SCAN_B + t;
    int v = (n < NN) ? deg[n] : 0;
    s[t] = v;
    __syncthreads();
    for (int d = 1; d < SCAN_B; d <<= 1) {
        int x = (t >= d) ? s[t - d] : 0;
        __syncthreads();
        s[t] += x;
        __syncthreads();
    }
    if (n < NN) off[n] = bpre[blockIdx.x] + s[t] - v;   // exclusive
}

// ---------- CSR fill, atomic-free (rank precomputed) ----------
__global__ void k_fill(const int* __restrict__ src, const int* __restrict__ dst,
                       const int* __restrict__ off, const int* __restrict__ rank,
                       int* __restrict__ elist) {
    int e = blockIdx.x * blockDim.x + threadIdx.x;
    if (e >= NE) return;
    elist[off[dst[e]] + rank[e]] = src[e];
}

// ---------- mean aggregation: one warp per node, unroll 2 (R4-measured) ----------
__global__ __launch_bounds__(256) void k_aggmean(
    const float* __restrict__ h, const int* __restrict__ elist,
    const int* __restrict__ off, const int* __restrict__ deg,
    float* __restrict__ mean) {
    int w = (blockIdx.x * blockDim.x + threadIdx.x) >> 5;
    int lane = threadIdx.x & 31;
    if (w >= NN) return;
    int beg = off[w], dg = deg[w];
    float2 a0 = make_float2(0.f, 0.f), a1 = a0;
    int i = beg, end = beg + dg;
    for (; i + 1 < end; i += 2) {
        int s0 = elist[i], s1 = elist[i + 1];
        float2 v0 = ((const float2*)(h + (size_t)s0 * DD))[lane];
        float2 v1 = ((const float2*)(h + (size_t)s1 * DD))[lane];
        a0.x += v0.x; a0.y += v0.y;
        a1.x += v1.x; a1.y += v1.y;
    }
    if (i < end) {
        int s0 = elist[i];
        float2 v0 = ((const float2*)(h + (size_t)s0 * DD))[lane];
        a0.x += v0.x; a0.y += v0.y;
    }
    float inv = 1.0f / (float)max(dg, 1);
    float2 o = make_float2((a0.x + a1.x) * inv, (a0.y + a1.y) * inv);
    ((float2*)(mean + (size_t)w * DD))[lane] = o;
}

// ---------- fused dual GEMM + bias + relu (R4 version — measured best) ----------
// out[n] = relu( mean[n] @ Wl^T + bl + h[n] @ Wr^T )
// 64 nodes x 64 dims per block, 256 threads, 4x4 micro-tile, FFMA2 (fma.rn.f32x2).
#define SA_STRIDE 68
__global__ __launch_bounds__(256) void k_linear(
    const float* __restrict__ mean, const float* __restrict__ h,
    const float* __restrict__ Wl, const float* __restrict__ bl,
    const float* __restrict__ Wr, float* __restrict__ out)
{
    extern __shared__ float smem[];
    float* sW = smem;                 // [128][64]
    float* sA = smem + 128 * 64;      // [128][SA_STRIDE] swizzled
    const int tid = threadIdx.x;

    // Weights transposed: sW[k][d] = Wl[d][k]; sW[64+k][d] = Wr[d][k]
    for (int i = tid; i < 64 * 64; i += 256) {
        int d = i >> 6, k = i & 63;
        sW[k * 64 + d]        = Wl[i];
        sW[(64 + k) * 64 + d] = Wr[i];
    }

    const int q  = tid & 15;     // node quad
    const int dq = tid >> 4;     // dim quad
    const int d0 = dq * 4;
    float4 bias = *(const float4*)&bl[d0];
    __syncthreads();

    const float4* m4 = (const float4*)mean;
    const float4* h4 = (const float4*)h;

    for (int n0 = blockIdx.x * 64; n0 < NN; n0 += gridDim.x * 64) {
        // Stage A^T swizzled: rows 0..63 = mean^T, 64..127 = h^T
        for (int i = tid; i < 64 * 16; i += 256) {
            int m = i >> 4, kq = i & 15;
            int n = n0 + m;
            float4 va = make_float4(0.f, 0.f, 0.f, 0.f), vh = va;
            if (n < NN) {
                va = m4[(size_t)n * 16 + kq];
                vh = h4[(size_t)n * 16 + kq];
            }
            int mb = m >> 2, mw = m & 3;
            int col = ((mb + kq) & 15) * 4 + mw;
            int k = kq * 4;
            sA[(k + 0) * SA_STRIDE + col] = va.x;
            sA[(k + 1) * SA_STRIDE + col] = va.y;
            sA[(k + 2) * SA_STRIDE + col] = va.z;
            sA[(k + 3) * SA_STRIDE + col] = va.w;
            sA[(64 + k + 0) * SA_STRIDE + col] = vh.x;
            sA[(64 + k + 1) * SA_STRIDE + col] = vh.y;
            sA[(64 + k + 2) * SA_STRIDE + col] = vh.z;
            sA[(64 + k + 3) * SA_STRIDE + col] = vh.w;
        }
        __syncthreads();

        // acc[node i][dim-pair j] : f32x2 over dims (d0+2j, d0+2j+1)
        u64 acc[4][2];
        u64 b01 = pk2(bias.x, bias.y);
        u64 b23 = pk2(bias.z, bias.w);
        #pragma unroll
        for (int i = 0; i < 4; i++) { acc[i][0] = b01; acc[i][1] = b23; }

        #pragma unroll
        for (int kq = 0; kq < 32; kq++) {
            int col = ((q + kq) & 15) * 4;
            const float* ar = &sA[(kq * 4) * SA_STRIDE + col];
            #pragma unroll
            for (int c = 0; c < 4; c++) {
                int k = kq * 4 + c;
                float4 a = *(const float4*)(ar + c * SA_STRIDE);
                float4 w = *(const float4*)&sW[k * 64 + d0];
                u64 w01 = pk2(w.x, w.y);
                u64 w23 = pk2(w.z, w.w);
                u64 ax = pk2(a.x, a.x);
                u64 ay = pk2(a.y, a.y);
                u64 az = pk2(a.z, a.z);
                u64 aw = pk2(a.w, a.w);
                ffma2(acc[0][0], ax, w01); ffma2(acc[0][1], ax, w23);
                ffma2(acc[1][0], ay, w01); ffma2(acc[1][1], ay, w23);
                ffma2(acc[2][0], az, w01); ffma2(acc[2][1], az, w23);
                ffma2(acc[3][0], aw, w01); ffma2(acc[3][1], aw, w23);
            }
        }

        int m0 = q * 4;
        #pragma unroll
        for (int i = 0; i < 4; i++) {
            int n = n0 + m0 + i;
            if (n < NN) {
                float o0, o1, o2, o3;
                upk2(o0, o1, acc[i][0]);
                upk2(o2, o3, acc[i][1]);
                float4 o = make_float4(fmaxf(o0, 0.f), fmaxf(o1, 0.f),
                                       fmaxf(o2, 0.f), fmaxf(o3, 0.f));
                *(float4*)&out[(size_t)n * DD + d0] = o;
            }
        }
        __syncthreads();
    }
}

// ---------- global mean pool ----------
__global__ void k_pool(const float* __restrict__ h, const int* __restrict__ batch,
                       float* __restrict__ pool, float* __restrict__ gcnt) {
    int t = blockIdx.x * blockDim.x + threadIdx.x;
    if (t >= NN * 4) return;
    int n = t >> 2, j = t & 3;
    int g = batch[n];
    const float4* hr = (const float4*)(h + (size_t)n * DD) + j * 4;
    float* p = pool + (size_t)g * DD + (size_t)j * 16;
    #pragma unroll
    for (int i = 0; i < 4; i++) red_v4(p + i * 4, hr[i]);
    if (j == 0) atomicAdd(&gcnt[g], 1.0f);
}

// ---------- classifier ----------
__global__ void k_out(const float* __restrict__ pool, const float* __restrict__ gcnt,
                      const float* __restrict__ Wout, const float* __restrict__ bout,
                      float* __restrict__ out) {
    int t = blockIdx.x * blockDim.x + threadIdx.x;
    if (t >= NG * 2) return;
    int g = t >> 1, c = t & 1;
    float inv = 1.0f / fmaxf(gcnt[g], 1.0f);
    float acc = bout[c];
    const float* p = pool + (size_t)g * DD;
    const float* w = Wout + (size_t)c * DD;
    #pragma unroll
    for (int k = 0; k < DD; k++) acc += p[k] * inv * w[k];
    out[(size_t)g * 2 + c] = acc;
}

extern "C" void kernel_launch(void* const* d_in, const int* in_sizes, int n_in,
                              void* d_out, int out_size) {
    const int*   x     = (const int*)d_in[0];
    const int*   ei    = (const int*)d_in[1];
    const int*   src   = ei;          // edge_index[0]
    const int*   dst   = ei + NE;     // edge_index[1]
    const int*   batch = (const int*)d_in[2];
    const float* emb   = (const float*)d_in[3];
    const float* W1l   = (const float*)d_in[4];
    const float* b1l   = (const float*)d_in[5];
    const float* W1r   = (const float*)d_in[6];
    const float* W2l   = (const float*)d_in[7];
    const float* b2l   = (const float*)d_in[8];
    const float* W2r   = (const float*)d_in[9];
    const float* Wout  = (const float*)d_in[10];
    const float* bout  = (const float*)d_in[11];
    float* out = (float*)d_out;

    float *h0, *h1, *h2, *mean, *pool, *gcnt;
    int *deg, *off, *rank, *elist, *bsum, *bpre;
    cudaGetSymbolAddress((void**)&h0,    g_h0);
    cudaGetSymbolAddress((void**)&h1,    g_h1);
    cudaGetSymbolAddress((void**)&h2,    g_h2);
    cudaGetSymbolAddress((void**)&mean,  g_agg);
    cudaGetSymbolAddress((void**)&pool,  g_pool);
    cudaGetSymbolAddress((void**)&gcnt,  g_gcnt);
    cudaGetSymbolAddress((void**)&deg,   g_deg);
    cudaGetSymbolAddress((void**)&off,   g_off);
    cudaGetSymbolAddress((void**)&rank,  g_rank);
    cudaGetSymbolAddress((void**)&elist, g_elist);
    cudaGetSymbolAddress((void**)&bsum,  g_bsum);
    cudaGetSymbolAddress((void**)&bpre,  g_bpre);

    const int SMEM_LIN = (128 * 64 + 128 * SA_STRIDE) * 4;   // 67584 bytes
    cudaFuncSetAttribute(k_linear, cudaFuncAttributeMaxDynamicSharedMemorySize, SMEM_LIN);

    cudaMemsetAsync(deg,  0, NN * sizeof(int));
    cudaMemsetAsync(pool, 0, (size_t)NG * DD * sizeof(float));
    cudaMemsetAsync(gcnt, 0, NG * sizeof(float));

    const int T = 256;

    // CSR build (reused by both layers)
    k_gather<<<(NN * 16 + T - 1) / T, T>>>(x, emb, h0);
    k_degrank<<<(NE + T - 1) / T, T>>>(dst, deg, rank);
    k_scan_part<<<SCAN_NB, SCAN_B>>>(deg, bsum);
    k_scan_mid<<<1, 128>>>(bsum, bpre);
    k_scan_add<<<SCAN_NB, SCAN_B>>>(deg, bpre, off);
    k_fill<<<(NE + T - 1) / T, T>>>(src, dst, off, rank, elist);

    // Layer 1
    k_aggmean<<<(NN * 32 + T - 1) / T, T>>>(h0, elist, off, deg, mean);
    k_linear<<<444, 256, SMEM_LIN>>>(mean, h0, W1l, b1l, W1r, h1);

    // Layer 2
    k_aggmean<<<(NN * 32 + T - 1) / T, T>>>(h1, elist, off, deg, mean);
    k_linear<<<444, 256, SMEM_LIN>>>(mean, h1, W2l, b2l, W2r, h2);

    // Pool + classify
    k_pool<<<(NN * 4 + T - 1) / T, T>>>(h2, batch, pool, gcnt);
    k_out<<<(NG * 2 + 127) / 128, 128>>>(pool, gcnt, Wout, bout, out);
}

// round 12
// speedup vs baseline: 1.7293x; 1.4231x over previous
#include <cuda_runtime.h>
#include <cuda_bf16.h>
#include <cuda_fp16.h>
#include <cstdint>

#define NN 100000
#define NE 1200000
#define NG 2048
#define DD 64
#define SCAN_B 1024
#define SCAN_NB 98   // 98*1024 = 100352 >= NN

// Scratch (allocation-free, __device__ globals)
__device__ float g_h0[(size_t)NN * DD];
__device__ float g_h1[(size_t)NN * DD];
__device__ float g_h2[(size_t)NN * DD];
__device__ float g_agg[(size_t)NN * DD];      // mean buffer
__device__ float g_pool[(size_t)NG * DD];
__device__ float g_gcnt[NG];
__device__ int   g_deg[NN];
__device__ int   g_off[NN];
__device__ int   g_cursor[NN];
__device__ int   g_elist[NE];
__device__ int   g_bsum[SCAN_NB];
__device__ int   g_bpre[SCAN_NB];

__device__ __forceinline__ void red_v4(float* p, float4 v) {
    asm volatile("red.global.add.v4.f32 [%0], {%1, %2, %3, %4};"
                 :: "l"(p), "f"(v.x), "f"(v.y), "f"(v.z), "f"(v.w) : "memory");
}

// ---------- h0[n] = emb[x[n]] ----------
__global__ void k_gather(const int* __restrict__ x, const float* __restrict__ emb,
                         float* __restrict__ h) {
    int t = blockIdx.x * blockDim.x + threadIdx.x;
    if (t >= NN * 16) return;
    int n = t >> 4, j = t & 15;
    const float4* e = (const float4*)(emb + (size_t)x[n] * DD);
    ((float4*)(h + (size_t)n * DD))[j] = e[j];
}

// ---------- deg[dst[e]] += 1 ----------
__global__ void k_deg(const int* __restrict__ dst, int* __restrict__ deg) {
    int e = blockIdx.x * blockDim.x + threadIdx.x;
    if (e < NE) atomicAdd(&deg[dst[e]], 1);
}

// ---------- CSR scan (3-kernel, R4-measured) ----------
__global__ void k_scan_part(const int* __restrict__ deg, int* __restrict__ bsum) {
    __shared__ int s[SCAN_B];
    int t = threadIdx.x, n = blockIdx.x * SCAN_B + t;
    s[t] = (n < NN) ? deg[n] : 0;
    __syncthreads();
    for (int d = SCAN_B / 2; d > 0; d >>= 1) {
        if (t < d) s[t] += s[t + d];
        __syncthreads();
    }
    if (t == 0) bsum[blockIdx.x] = s[0];
}

__global__ void k_scan_mid(const int* __restrict__ bsum, int* __restrict__ bpre) {
    __shared__ int s[128];
    int t = threadIdx.x;
    int v = (t < SCAN_NB) ? bsum[t] : 0;
    s[t] = v;
    __syncthreads();
    for (int d = 1; d < 128; d <<= 1) {
        int x = (t >= d) ? s[t - d] : 0;
        __syncthreads();
        s[t] += x;
        __syncthreads();
    }
    if (t < SCAN_NB) bpre[t] = s[t] - v;   // exclusive
}

__global__ void k_scan_add(const int* __restrict__ deg, const int* __restrict__ bpre,
                           int* __restrict__ off) {
    __shared__ int s[SCAN_B];
    int t = threadIdx.x, n = blockIdx.x * SCAN_B + t;
    int v = (n < NN) ? deg[n] : 0;
    s[t] = v;
    __syncthreads();
    for (int d = 1; d < SCAN_B; d <<= 1) {
        int x = (t >= d) ? s[t - d] : 0;
        __syncthreads();
        s[t] += x;
        __syncthreads();
    }
    if (n < NN) off[n] = bpre[blockIdx.x] + s[t] - v;   // exclusive
}

// ---------- CSR fill (R4 atomic version) ----------
__global__ void k_fill(const int* __restrict__ src, const int* __restrict__ dst,
                       const int* __restrict__ off, int* __restrict__ cursor,
                       int* __restrict__ elist) {
    int e = blockIdx.x * blockDim.x + threadIdx.x;
    if (e >= NE) return;
    int d = dst[e];
    int p = atomicAdd(&cursor[d], 1);
    elist[off[d] + p] = src[e];
}

// ---------- mean aggregation: one warp per node, unroll 2 (R4-measured) ----------
__global__ __launch_bounds__(256) void k_aggmean(
    const float* __restrict__ h, const int* __restrict__ elist,
    const int* __restrict__ off, const int* __restrict__ deg,
    float* __restrict__ mean) {
    int w = (blockIdx.x * blockDim.x + threadIdx.x) >> 5;
    int lane = threadIdx.x & 31;
    if (w >= NN) return;
    int beg = off[w], dg = deg[w];
    float2 a0 = make_float2(0.f, 0.f), a1 = a0;
    int i = beg, end = beg + dg;
    for (; i + 1 < end; i += 2) {
        int s0 = elist[i], s1 = elist[i + 1];
        float2 v0 = ((const float2*)(h + (size_t)s0 * DD))[lane];
        float2 v1 = ((const float2*)(h + (size_t)s1 * DD))[lane];
        a0.x += v0.x; a0.y += v0.y;
        a1.x += v1.x; a1.y += v1.y;
    }
    if (i < end) {
        int s0 = elist[i];
        float2 v0 = ((const float2*)(h + (size_t)s0 * DD))[lane];
        a0.x += v0.x; a0.y += v0.y;
    }
    float inv = 1.0f / (float)max(dg, 1);
    float2 o = make_float2((a0.x + a1.x) * inv, (a0.y + a1.y) * inv);
    ((float2*)(mean + (size_t)w * DD))[lane] = o;
}

// ---------- tensor-core dual GEMM + bias + relu ----------
// out[n] = relu( mean[n] @ Wl^T + bl + h[n] @ Wr^T )
// A = [mean | h] fp16 [128 x 128], B = [Wl | Wr] fp16 [64 x 128] (row d = output dim,
// contiguous in k => col-major kxn as mma row.col requires).
// mma.sync.m16n8k16.row.col.f32.f16.f16.f32; block = 128 nodes, 8 warps x 16-row slabs.
#define ASTR 136   // halves per row (272B: 16B bank rotation, conflict-free ldmatrix)

__device__ __forceinline__ uint32_t smem_u32(const void* p) {
    uint32_t a;
    asm("{ .reg .u64 t; cvta.to.shared.u64 t, %1; cvt.u32.u64 %0, t; }" : "=r"(a) : "l"(p));
    return a;
}
__device__ __forceinline__ void ldm_x4(uint32_t& r0, uint32_t& r1, uint32_t& r2,
                                       uint32_t& r3, uint32_t addr) {
    asm volatile("ldmatrix.sync.aligned.m8n8.x4.shared.b16 {%0,%1,%2,%3}, [%4];"
                 : "=r"(r0), "=r"(r1), "=r"(r2), "=r"(r3) : "r"(addr));
}
__device__ __forceinline__ void mma16816(float* c, uint32_t a0, uint32_t a1,
                                         uint32_t a2, uint32_t a3,
                                         uint32_t b0, uint32_t b1) {
    asm volatile("mma.sync.aligned.m16n8k16.row.col.f32.f16.f16.f32 "
                 "{%0,%1,%2,%3}, {%4,%5,%6,%7}, {%8,%9}, {%0,%1,%2,%3};"
                 : "+f"(c[0]), "+f"(c[1]), "+f"(c[2]), "+f"(c[3])
                 : "r"(a0), "r"(a1), "r"(a2), "r"(a3), "r"(b0), "r"(b1));
}

__global__ __launch_bounds__(256) void k_linear(
    const float* __restrict__ mean, const float* __restrict__ h,
    const float* __restrict__ Wl, const float* __restrict__ bl,
    const float* __restrict__ Wr, float* __restrict__ out)
{
    extern __shared__ __half smem[];
    __half* sB = smem;                 // [64][ASTR]
    __half* sA = smem + 64 * ASTR;     // [128][ASTR]
    const int tid  = threadIdx.x;
    const int w    = tid >> 5;
    const int lane = tid & 31;
    const int n0   = blockIdx.x * 128;

    // Stage B: sB[d][k] = Wl[d][k] (k<64), Wr[d][k-64] (k>=64), fp16
    for (int i = tid; i < 64 * 64; i += 256) {
        int d = i >> 6, k = i & 63;
        sB[d * ASTR + k]      = __float2half(Wl[i]);
        sB[d * ASTR + 64 + k] = __float2half(Wr[i]);
    }

    // Stage A: sA[m][0..63] = mean[n0+m], sA[m][64..127] = h[n0+m], fp16
    const float4* m4 = (const float4*)mean;
    const float4* h4 = (const float4*)h;
    for (int i = tid; i < 128 * 16; i += 256) {
        int m = i >> 4, qq = i & 15;   // qq indexes float4 within 64 floats
        int n = n0 + m;
        float4 vm = make_float4(0.f, 0.f, 0.f, 0.f), vh = vm;
        if (n < NN) {
            vm = m4[(size_t)n * 16 + qq];
            vh = h4[(size_t)n * 16 + qq];
        }
        __half2* pa = (__half2*)(sA + m * ASTR + qq * 4);
        pa[0] = __floats2half2_rn(vm.x, vm.y);
        pa[1] = __floats2half2_rn(vm.z, vm.w);
        __half2* ph = (__half2*)(sA + m * ASTR + 64 + qq * 4);
        ph[0] = __floats2half2_rn(vh.x, vh.y);
        ph[1] = __floats2half2_rn(vh.z, vh.w);
    }

    // Accumulators: 8 n-frags (16x8 each) covering N=64; init with bias.
    float c[8][4];
    {
        int cb = (lane & 3) * 2;
        #pragma unroll
        for (int nf = 0; nf < 8; nf++) {
            float b0 = bl[nf * 8 + cb];
            float b1 = bl[nf * 8 + cb + 1];
            c[nf][0] = b0; c[nf][1] = b1;
            c[nf][2] = b0; c[nf][3] = b1;
        }
    }
    __syncthreads();

    // ldmatrix lane addresses
    uint32_t sA_u = smem_u32(sA);
    uint32_t sB_u = smem_u32(sB);
    int a_row = w * 16 + (lane & 15);
    uint32_t a_addr = sA_u + (uint32_t)(a_row * ASTR + ((lane >> 4) << 3)) * 2;
    int b_row_base = (lane & 7) + ((lane >> 3) & 1) * 8;
    uint32_t b_col = ((lane >> 4) << 3);
    uint32_t b_addr0 = sB_u + (uint32_t)((b_row_base +  0) * ASTR + b_col) * 2;
    uint32_t b_addr1 = sB_u + (uint32_t)((b_row_base + 16) * ASTR + b_col) * 2;
    uint32_t b_addr2 = sB_u + (uint32_t)((b_row_base + 32) * ASTR + b_col) * 2;
    uint32_t b_addr3 = sB_u + (uint32_t)((b_row_base + 48) * ASTR + b_col) * 2;

    #pragma unroll
    for (int ks = 0; ks < 8; ks++) {
        uint32_t koff = ks * 32;   // 16 halves = 32 bytes per k-step
        uint32_t a0, a1, a2, a3;
        ldm_x4(a0, a1, a2, a3, a_addr + koff);
        uint32_t b0, b1, b2, b3;
        ldm_x4(b0, b1, b2, b3, b_addr0 + koff);
        mma16816(c[0], a0, a1, a2, a3, b0, b2);
        mma16816(c[1], a0, a1, a2, a3, b1, b3);
        ldm_x4(b0, b1, b2, b3, b_addr1 + koff);
        mma16816(c[2], a0, a1, a2, a3, b0, b2);
        mma16816(c[3], a0, a1, a2, a3, b1, b3);
        ldm_x4(b0, b1, b2, b3, b_addr2 + koff);
        mma16816(c[4], a0, a1, a2, a3, b0, b2);
        mma16816(c[5], a0, a1, a2, a3, b1, b3);
        ldm_x4(b0, b1, b2, b3, b_addr3 + koff);
        mma16816(c[6], a0, a1, a2, a3, b0, b2);
        mma16816(c[7], a0, a1, a2, a3, b1, b3);
    }

    // Store with relu: thread holds rows (w*16 + lane/4) and (+8), cols nf*8 + (lane%4)*2
    int r0 = n0 + w * 16 + (lane >> 2);
    int r1 = r0 + 8;
    int cb = (lane & 3) * 2;
    if (r0 < NN) {
        float* o = out + (size_t)r0 * DD;
        #pragma unroll
        for (int nf = 0; nf < 8; nf++) {
            float2 v = make_float2(fmaxf(c[nf][0], 0.f), fmaxf(c[nf][1], 0.f));
            *(float2*)&o[nf * 8 + cb] = v;
        }
    }
    if (r1 < NN) {
        float* o = out + (size_t)r1 * DD;
        #pragma unroll
        for (int nf = 0; nf < 8; nf++) {
            float2 v = make_float2(fmaxf(c[nf][2], 0.f), fmaxf(c[nf][3], 0.f));
            *(float2*)&o[nf * 8 + cb] = v;
        }
    }
}

// ---------- global mean pool ----------
__global__ void k_pool(const float* __restrict__ h, const int* __restrict__ batch,
                       float* __restrict__ pool, float* __restrict__ gcnt) {
    int t = blockIdx.x * blockDim.x + threadIdx.x;
    if (t >= NN * 4) return;
    int n = t >> 2, j = t & 3;
    int g = batch[n];
    const float4* hr = (const float4*)(h + (size_t)n * DD) + j * 4;
    float* p = pool + (size_t)g * DD + (size_t)j * 16;
    #pragma unroll
    for (int i = 0; i < 4; i++) red_v4(p + i * 4, hr[i]);
    if (j == 0) atomicAdd(&gcnt[g], 1.0f);
}

// ---------- classifier ----------
__global__ void k_out(const float* __restrict__ pool, const float* __restrict__ gcnt,
                      const float* __restrict__ Wout, const float* __restrict__ bout,
                      float* __restrict__ out) {
    int t = blockIdx.x * blockDim.x + threadIdx.x;
    if (t >= NG * 2) return;
    int g = t >> 1, c = t & 1;
    float inv = 1.0f / fmaxf(gcnt[g], 1.0f);
    float acc = bout[c];
    const float* p = pool + (size_t)g * DD;
    const float* w = Wout + (size_t)c * DD;
    #pragma unroll
    for (int k = 0; k < DD; k++) acc += p[k] * inv * w[k];
    out[(size_t)g * 2 + c] = acc;
}

extern "C" void kernel_launch(void* const* d_in, const int* in_sizes, int n_in,
                              void* d_out, int out_size) {
    const int*   x     = (const int*)d_in[0];
    const int*   ei    = (const int*)d_in[1];
    const int*   src   = ei;          // edge_index[0]
    const int*   dst   = ei + NE;     // edge_index[1]
    const int*   batch = (const int*)d_in[2];
    const float* emb   = (const float*)d_in[3];
    const float* W1l   = (const float*)d_in[4];
    const float* b1l   = (const float*)d_in[5];
    const float* W1r   = (const float*)d_in[6];
    const float* W2l   = (const float*)d_in[7];
    const float* b2l   = (const float*)d_in[8];
    const float* W2r   = (const float*)d_in[9];
    const float* Wout  = (const float*)d_in[10];
    const float* bout  = (const float*)d_in[11];
    float* out = (float*)d_out;

    float *h0, *h1, *h2, *mean, *pool, *gcnt;
    int *deg, *off, *cursor, *elist, *bsum, *bpre;
    cudaGetSymbolAddress((void**)&h0,     g_h0);
    cudaGetSymbolAddress((void**)&h1,     g_h1);
    cudaGetSymbolAddress((void**)&h2,     g_h2);
    cudaGetSymbolAddress((void**)&mean,   g_agg);
    cudaGetSymbolAddress((void**)&pool,   g_pool);
    cudaGetSymbolAddress((void**)&gcnt,   g_gcnt);
    cudaGetSymbolAddress((void**)&deg,    g_deg);
    cudaGetSymbolAddress((void**)&off,    g_off);
    cudaGetSymbolAddress((void**)&cursor, g_cursor);
    cudaGetSymbolAddress((void**)&elist,  g_elist);
    cudaGetSymbolAddress((void**)&bsum,   g_bsum);
    cudaGetSymbolAddress((void**)&bpre,   g_bpre);

    const int SMEM_LIN = (64 * ASTR + 128 * ASTR) * 2;   // 52224 bytes
    cudaFuncSetAttribute(k_linear, cudaFuncAttributeMaxDynamicSharedMemorySize, SMEM_LIN);

    cudaMemsetAsync(deg,    0, NN * sizeof(int));
    cudaMemsetAsync(cursor, 0, NN * sizeof(int));
    cudaMemsetAsync(pool,   0, (size_t)NG * DD * sizeof(float));
    cudaMemsetAsync(gcnt,   0, NG * sizeof(float));

    const int T = 256;
    const int LIN_GRID = (NN + 127) / 128;   // 782

    // CSR build (reused by both layers)
    k_gather<<<(NN * 16 + T - 1) / T, T>>>(x, emb, h0);
    k_deg<<<(NE + T - 1) / T, T>>>(dst, deg);
    k_scan_part<<<SCAN_NB, SCAN_B>>>(deg, bsum);
    k_scan_mid<<<1, 128>>>(bsum, bpre);
    k_scan_add<<<SCAN_NB, SCAN_B>>>(deg, bpre, off);
    k_fill<<<(NE + T - 1) / T, T>>>(src, dst, off, cursor, elist);

    // Layer 1
    k_aggmean<<<(NN * 32 + T - 1) / T, T>>>(h0, elist, off, deg, mean);
    k_linear<<<LIN_GRID, 256, SMEM_LIN>>>(mean, h0, W1l, b1l, W1r, h1);

    // Layer 2
    k_aggmean<<<(NN * 32 + T - 1) / T, T>>>(h1, elist, off, deg, mean);
    k_linear<<<LIN_GRID, 256, SMEM_LIN>>>(mean, h1, W2l, b2l, W2r, h2);

    // Pool + classify
    k_pool<<<(NN * 4 + T - 1) / T, T>>>(h2, batch, pool, gcnt);
    k_out<<<(NG * 2 + 127) / 128, 128>>>(pool, gcnt, Wout, bout, out);
}

// round 14
// speedup vs baseline: 1.9300x; 1.1161x over previous
#include <cuda_runtime.h>
#include <cuda_bf16.h>
#include <cuda_fp16.h>
#include <cstdint>

#define NN 100000
#define NE 1200000
#define NG 2048
#define DD 64
#define SCAN_B 1024
#define SCAN_NB 98   // 98*1024 = 100352 >= NN

// Scratch (allocation-free, __device__ globals). All h storage is fp16.
__device__ __align__(16) __half g_h16_0[(size_t)NN * DD];
__device__ __align__(16) __half g_h16_1[(size_t)NN * DD];
__device__ __align__(16) __half g_h16_2[(size_t)NN * DD];
__device__ __align__(16) __half g_mean16[(size_t)NN * DD];
__device__ float g_pool[(size_t)NG * DD];
__device__ float g_gcnt[NG];
__device__ int   g_deg[NN];
__device__ int   g_off[NN];
__device__ int   g_cursor[NN];
__device__ int   g_elist[NE];
__device__ int   g_bsum[SCAN_NB];
__device__ int   g_bpre[SCAN_NB];

__device__ __forceinline__ void red_v4(float* p, float4 v) {
    asm volatile("red.global.add.v4.f32 [%0], {%1, %2, %3, %4};"
                 :: "l"(p), "f"(v.x), "f"(v.y), "f"(v.z), "f"(v.w) : "memory");
}

// ---------- h0[n] = fp16(emb[x[n]]) ----------
__global__ void k_gather(const int* __restrict__ x, const float* __restrict__ emb,
                         __half* __restrict__ h) {
    int t = blockIdx.x * blockDim.x + threadIdx.x;
    if (t >= NN * 8) return;
    int n = t >> 3, j = t & 7;   // j: 8-float chunk
    const float4* e = (const float4*)(emb + (size_t)x[n] * DD) + j * 2;
    float4 v0 = e[0], v1 = e[1];
    uint4 o;
    __half2* op = (__half2*)&o;
    op[0] = __floats2half2_rn(v0.x, v0.y);
    op[1] = __floats2half2_rn(v0.z, v0.w);
    op[2] = __floats2half2_rn(v1.x, v1.y);
    op[3] = __floats2half2_rn(v1.z, v1.w);
    *(uint4*)(h + (size_t)n * DD + j * 8) = o;
}

// ---------- deg[dst[e]] += 1 ----------
__global__ void k_deg(const int* __restrict__ dst, int* __restrict__ deg) {
    int e = blockIdx.x * blockDim.x + threadIdx.x;
    if (e < NE) atomicAdd(&deg[dst[e]], 1);
}

// ---------- CSR scan (3-kernel, R4-measured) ----------
__global__ void k_scan_part(const int* __restrict__ deg, int* __restrict__ bsum) {
    __shared__ int s[SCAN_B];
    int t = threadIdx.x, n = blockIdx.x * SCAN_B + t;
    s[t] = (n < NN) ? deg[n] : 0;
    __syncthreads();
    for (int d = SCAN_B / 2; d > 0; d >>= 1) {
        if (t < d) s[t] += s[t + d];
        __syncthreads();
    }
    if (t == 0) bsum[blockIdx.x] = s[0];
}

__global__ void k_scan_mid(const int* __restrict__ bsum, int* __restrict__ bpre) {
    __shared__ int s[128];
    int t = threadIdx.x;
    int v = (t < SCAN_NB) ? bsum[t] : 0;
    s[t] = v;
    __syncthreads();
    for (int d = 1; d < 128; d <<= 1) {
        int x = (t >= d) ? s[t - d] : 0;
        __syncthreads();
        s[t] += x;
        __syncthreads();
    }
    if (t < SCAN_NB) bpre[t] = s[t] - v;   // exclusive
}

__global__ void k_scan_add(const int* __restrict__ deg, const int* __restrict__ bpre,
                           int* __restrict__ off) {
    __shared__ int s[SCAN_B];
    int t = threadIdx.x, n = blockIdx.x * SCAN_B + t;
    int v = (n < NN) ? deg[n] : 0;
    s[t] = v;
    __syncthreads();
    for (int d = 1; d < SCAN_B; d <<= 1) {
        int x = (t >= d) ? s[t - d] : 0;
        __syncthreads();
        s[t] += x;
        __syncthreads();
    }
    if (n < NN) off[n] = bpre[blockIdx.x] + s[t] - v;   // exclusive
}

// ---------- CSR fill ----------
__global__ void k_fill(const int* __restrict__ src, const int* __restrict__ dst,
                       const int* __restrict__ off, int* __restrict__ cursor,
                       int* __restrict__ elist) {
    int e = blockIdx.x * blockDim.x + threadIdx.x;
    if (e >= NE) return;
    int d = dst[e];
    int p = atomicAdd(&cursor[d], 1);
    elist[off[d] + p] = src[e];
}

// ---------- mean aggregation: one warp per node, fp16 gather, fp32 accum ----------
__global__ __launch_bounds__(256) void k_aggmean(
    const __half* __restrict__ h, const int* __restrict__ elist,
    const int* __restrict__ off, const int* __restrict__ deg,
    __half* __restrict__ mean) {
    int w = (blockIdx.x * blockDim.x + threadIdx.x) >> 5;
    int lane = threadIdx.x & 31;
    if (w >= NN) return;
    int beg = off[w], dg = deg[w];
    float2 a0 = make_float2(0.f, 0.f), a1 = a0;
    int i = beg, end = beg + dg;
    for (; i + 1 < end; i += 2) {
        int s0 = elist[i], s1 = elist[i + 1];
        float2 v0 = __half22float2(((const __half2*)(h + (size_t)s0 * DD))[lane]);
        float2 v1 = __half22float2(((const __half2*)(h + (size_t)s1 * DD))[lane]);
        a0.x += v0.x; a0.y += v0.y;
        a1.x += v1.x; a1.y += v1.y;
    }
    if (i < end) {
        int s0 = elist[i];
        float2 v0 = __half22float2(((const __half2*)(h + (size_t)s0 * DD))[lane]);
        a0.x += v0.x; a0.y += v0.y;
    }
    float inv = 1.0f / (float)max(dg, 1);
    ((__half2*)(mean + (size_t)w * DD))[lane] =
        __floats2half2_rn((a0.x + a1.x) * inv, (a0.y + a1.y) * inv);
}

// ---------- tensor-core dual GEMM + bias + relu (fp16 in / fp16 out) ----------
// out[n] = relu( mean[n] @ Wl^T + bl + h[n] @ Wr^T ), fp32 accumulate.
// A = [mean | h] fp16 [128 x 128], B = [Wl | Wr] fp16 [64 x 128] (k-contiguous = col).
// mma.sync.m16n8k16.row.col.f32.f16.f16.f32; block = 128 nodes, 8 warps x 16-row slabs.
#define ASTR 136   // halves per row (272B: 16B bank rotation, conflict-free ldmatrix)

__device__ __forceinline__ uint32_t smem_u32(const void* p) {
    uint32_t a;
    asm("{ .reg .u64 t; cvta.to.shared.u64 t, %1; cvt.u32.u64 %0, t; }" : "=r"(a) : "l"(p));
    return a;
}
__device__ __forceinline__ void ldm_x4(uint32_t& r0, uint32_t& r1, uint32_t& r2,
                                       uint32_t& r3, uint32_t addr) {
    asm volatile("ldmatrix.sync.aligned.m8n8.x4.shared.b16 {%0,%1,%2,%3}, [%4];"
                 : "=r"(r0), "=r"(r1), "=r"(r2), "=r"(r3) : "r"(addr));
}
__device__ __forceinline__ void mma16816(float* c, uint32_t a0, uint32_t a1,
                                         uint32_t a2, uint32_t a3,
                                         uint32_t b0, uint32_t b1) {
    asm volatile("mma.sync.aligned.m16n8k16.row.col.f32.f16.f16.f32 "
                 "{%0,%1,%2,%3}, {%4,%5,%6,%7}, {%8,%9}, {%0,%1,%2,%3};"
                 : "+f"(c[0]), "+f"(c[1]), "+f"(c[2]), "+f"(c[3])
                 : "r"(a0), "r"(a1), "r"(a2), "r"(a3), "r"(b0), "r"(b1));
}

__global__ __launch_bounds__(256) void k_linear(
    const __half* __restrict__ mean, const __half* __restrict__ h,
    const float* __restrict__ Wl, const float* __restrict__ bl,
    const float* __restrict__ Wr, __half* __restrict__ out)
{
    extern __shared__ __half smem[];
    __half* sB = smem;                 // [64][ASTR]
    __half* sA = smem + 64 * ASTR;     // [128][ASTR]
    const int tid  = threadIdx.x;
    const int w    = tid >> 5;
    const int lane = tid & 31;
    const int n0   = blockIdx.x * 128;

    // Stage B: sB[d][k] = Wl[d][k] (k<64), Wr[d][k-64] (k>=64), fp16
    for (int i = tid; i < 64 * 64; i += 256) {
        int d = i >> 6, k = i & 63;
        sB[d * ASTR + k]      = __float2half(Wl[i]);
        sB[d * ASTR + 64 + k] = __float2half(Wr[i]);
    }

    // Stage A: straight fp16 16B copies. qq<8 -> mean chunk qq, else h chunk qq-8.
    for (int i = tid; i < 128 * 16; i += 256) {
        int m = i >> 4, qq = i & 15;
        int n = n0 + m;
        uint4 v = make_uint4(0u, 0u, 0u, 0u);
        if (n < NN) {
            const __half* srcp = (qq < 8)
                ? (mean + (size_t)n * DD + qq * 8)
                : (h    + (size_t)n * DD + (qq - 8) * 8);
            v = *(const uint4*)srcp;
        }
        *(uint4*)(sA + m * ASTR + qq * 8) = v;
    }

    // Accumulators: 8 n-frags (16x8 each) covering N=64; init with bias.
    float c[8][4];
    {
        int cb = (lane & 3) * 2;
        #pragma unroll
        for (int nf = 0; nf < 8; nf++) {
            float b0 = bl[nf * 8 + cb];
            float b1 = bl[nf * 8 + cb + 1];
            c[nf][0] = b0; c[nf][1] = b1;
            c[nf][2] = b0; c[nf][3] = b1;
        }
    }
    __syncthreads();

    // ldmatrix lane addresses
    uint32_t sA_u = smem_u32(sA);
    uint32_t sB_u = smem_u32(sB);
    int a_row = w * 16 + (lane & 15);
    uint32_t a_addr = sA_u + (uint32_t)(a_row * ASTR + ((lane >> 4) << 3)) * 2;
    int b_row_base = (lane & 7) + ((lane >> 3) & 1) * 8;
    uint32_t b_col = ((lane >> 4) << 3);
    uint32_t b_addr0 = sB_u + (uint32_t)((b_row_base +  0) * ASTR + b_col) * 2;
    uint32_t b_addr1 = sB_u + (uint32_t)((b_row_base + 16) * ASTR + b_col) * 2;
    uint32_t b_addr2 = sB_u + (uint32_t)((b_row_base + 32) * ASTR + b_col) * 2;
    uint32_t b_addr3 = sB_u + (uint32_t)((b_row_base + 48) * ASTR + b_col) * 2;

    #pragma unroll
    for (int ks = 0; ks < 8; ks++) {
        uint32_t koff = ks * 32;   // 16 halves = 32 bytes per k-step
        uint32_t a0, a1, a2, a3;
        ldm_x4(a0, a1, a2, a3, a_addr + koff);
        uint32_t b0, b1, b2, b3;
        ldm_x4(b0, b1, b2, b3, b_addr0 + koff);
        mma16816(c[0], a0, a1, a2, a3, b0, b2);
        mma16816(c[1], a0, a1, a2, a3, b1, b3);
        ldm_x4(b0, b1, b2, b3, b_addr1 + koff);
        mma16816(c[2], a0, a1, a2, a3, b0, b2);
        mma16816(c[3], a0, a1, a2, a3, b1, b3);
        ldm_x4(b0, b1, b2, b3, b_addr2 + koff);
        mma16816(c[4], a0, a1, a2, a3, b0, b2);
        mma16816(c[5], a0, a1, a2, a3, b1, b3);
        ldm_x4(b0, b1, b2, b3, b_addr3 + koff);
        mma16816(c[6], a0, a1, a2, a3, b0, b2);
        mma16816(c[7], a0, a1, a2, a3, b1, b3);
    }

    // Store fp16 with relu: rows (w*16 + lane/4) and (+8), cols nf*8 + (lane%4)*2
    int r0 = n0 + w * 16 + (lane >> 2);
    int r1 = r0 + 8;
    int cb = (lane & 3) * 2;
    if (r0 < NN) {
        __half* o = out + (size_t)r0 * DD;
        #pragma unroll
        for (int nf = 0; nf < 8; nf++)
            *(__half2*)&o[nf * 8 + cb] =
                __floats2half2_rn(fmaxf(c[nf][0], 0.f), fmaxf(c[nf][1], 0.f));
    }
    if (r1 < NN) {
        __half* o = out + (size_t)r1 * DD;
        #pragma unroll
        for (int nf = 0; nf < 8; nf++)
            *(__half2*)&o[nf * 8 + cb] =
                __floats2half2_rn(fmaxf(c[nf][2], 0.f), fmaxf(c[nf][3], 0.f));
    }
}

// ---------- global mean pool (fp16 read, fp32 accumulate) ----------
// Each thread covers 16 floats (quarter row) => TWO uint4 loads (16 halves).
__global__ void k_pool(const __half* __restrict__ h, const int* __restrict__ batch,
                       float* __restrict__ pool, float* __restrict__ gcnt) {
    int t = blockIdx.x * blockDim.x + threadIdx.x;
    if (t >= NN * 4) return;
    int n = t >> 2, j = t & 3;
    int g = batch[n];
    const __half* hb = h + (size_t)n * DD + j * 16;
    uint4 raw[2];
    raw[0] = *(const uint4*)hb;
    raw[1] = *(const uint4*)(hb + 8);
    const __half2* hp = (const __half2*)raw;   // 8 half2 = 16 halves
    float* p = pool + (size_t)g * DD + (size_t)j * 16;
    #pragma unroll
    for (int i = 0; i < 4; i++) {
        float2 lo = __half22float2(hp[2 * i]);
        float2 hi = __half22float2(hp[2 * i + 1]);
        red_v4(p + i * 4, make_float4(lo.x, lo.y, hi.x, hi.y));
    }
    if (j == 0) atomicAdd(&gcnt[g], 1.0f);
}

// ---------- classifier ----------
__global__ void k_out(const float* __restrict__ pool, const float* __restrict__ gcnt,
                      const float* __restrict__ Wout, const float* __restrict__ bout,
                      float* __restrict__ out) {
    int t = blockIdx.x * blockDim.x + threadIdx.x;
    if (t >= NG * 2) return;
    int g = t >> 1, c = t & 1;
    float inv = 1.0f / fmaxf(gcnt[g], 1.0f);
    float acc = bout[c];
    const float* p = pool + (size_t)g * DD;
    const float* w = Wout + (size_t)c * DD;
    #pragma unroll
    for (int k = 0; k < DD; k++) acc += p[k] * inv * w[k];
    out[(size_t)g * 2 + c] = acc;
}

extern "C" void kernel_launch(void* const* d_in, const int* in_sizes, int n_in,
                              void* d_out, int out_size) {
    const int*   x     = (const int*)d_in[0];
    const int*   ei    = (const int*)d_in[1];
    const int*   src   = ei;          // edge_index[0]
    const int*   dst   = ei + NE;     // edge_index[1]
    const int*   batch = (const int*)d_in[2];
    const float* emb   = (const float*)d_in[3];
    const float* W1l   = (const float*)d_in[4];
    const float* b1l   = (const float*)d_in[5];
    const float* W1r   = (const float*)d_in[6];
    const float* W2l   = (const float*)d_in[7];
    const float* b2l   = (const float*)d_in[8];
    const float* W2r   = (const float*)d_in[9];
    const float* Wout  = (const float*)d_in[10];
    const float* bout  = (const float*)d_in[11];
    float* out = (float*)d_out;

    __half *h0, *h1, *h2, *mean16;
    float *pool, *gcnt;
    int *deg, *off, *cursor, *elist, *bsum, *bpre;
    cudaGetSymbolAddress((void**)&h0,     g_h16_0);
    cudaGetSymbolAddress((void**)&h1,     g_h16_1);
    cudaGetSymbolAddress((void**)&h2,     g_h16_2);
    cudaGetSymbolAddress((void**)&mean16, g_mean16);
    cudaGetSymbolAddress((void**)&pool,   g_pool);
    cudaGetSymbolAddress((void**)&gcnt,   g_gcnt);
    cudaGetSymbolAddress((void**)&deg,    g_deg);
    cudaGetSymbolAddress((void**)&off,    g_off);
    cudaGetSymbolAddress((void**)&cursor, g_cursor);
    cudaGetSymbolAddress((void**)&elist,  g_elist);
    cudaGetSymbolAddress((void**)&bsum,   g_bsum);
    cudaGetSymbolAddress((void**)&bpre,   g_bpre);

    const int SMEM_LIN = (64 * ASTR + 128 * ASTR) * 2;   // 52224 bytes
    cudaFuncSetAttribute(k_linear, cudaFuncAttributeMaxDynamicSharedMemorySize, SMEM_LIN);

    cudaMemsetAsync(deg,    0, NN * sizeof(int));
    cudaMemsetAsync(cursor, 0, NN * sizeof(int));
    cudaMemsetAsync(pool,   0, (size_t)NG * DD * sizeof(float));
    cudaMemsetAsync(gcnt,   0, NG * sizeof(float));

    const int T = 256;
    const int LIN_GRID = (NN + 127) / 128;   // 782

    // CSR build (reused by both layers)
    k_gather<<<(NN * 8 + T - 1) / T, T>>>(x, emb, h0);
    k_deg<<<(NE + T - 1) / T, T>>>(dst, deg);
    k_scan_part<<<SCAN_NB, SCAN_B>>>(deg, bsum);
    k_scan_mid<<<1, 128>>>(bsum, bpre);
    k_scan_add<<<SCAN_NB, SCAN_B>>>(deg, bpre, off);
    k_fill<<<(NE + T - 1) / T, T>>>(src, dst, off, cursor, elist);

    // Layer 1
    k_aggmean<<<(NN * 32 + T - 1) / T, T>>>(h0, elist, off, deg, mean16);
    k_linear<<<LIN_GRID, 256, SMEM_LIN>>>(mean16, h0, W1l, b1l, W1r, h1);

    // Layer 2
    k_aggmean<<<(NN * 32 + T - 1) / T, T>>>(h1, elist, off, deg, mean16);
    k_linear<<<LIN_GRID, 256, SMEM_LIN>>>(mean16, h1, W2l, b2l, W2r, h2);

    // Pool + classify
    k_pool<<<(NN * 4 + T - 1) / T, T>>>(h2, batch, pool, gcnt);
    k_out<<<(NG * 2 + 127) / 128, 128>>>(pool, gcnt, Wout, bout, out);
}

// round 15
// speedup vs baseline: 2.2536x; 1.1676x over previous
#include <cuda_runtime.h>
#include <cuda_bf16.h>
#include <cuda_fp16.h>
#include <cstdint>

#define NN 100000
#define NE 1200000
#define NG 2048
#define DD 64
#define SCAN_B 1024
#define SCAN_NB 98   // 98*1024 = 100352 >= NN

// Scratch (allocation-free, __device__ globals). All h storage is fp16.
__device__ __align__(16) __half g_h16_0[(size_t)NN * DD];
__device__ __align__(16) __half g_h16_1[(size_t)NN * DD];
__device__ __align__(16) __half g_mean16[(size_t)NN * DD];
__device__ float g_poolcnt[(size_t)NG * DD + NG];   // pool | gcnt
__device__ int   g_degcur[2 * NN];                  // deg | cursor
__device__ int   g_off[NN];
__device__ int   g_elist[NE];
__device__ int   g_scanstat[2 * SCAN_NB];           // agg | inc (init 0xFF)

__device__ __forceinline__ void red_v2(float* p, float a, float b) {
    asm volatile("red.global.add.v2.f32 [%0], {%1, %2};"
                 :: "l"(p), "f"(a), "f"(b) : "memory");
}

// ---------- fused: h0[n] = fp16(emb[x[n]])  AND  deg[dst[e]] += 1 ----------
__global__ void k_gatherdeg(const int* __restrict__ x, const float* __restrict__ emb,
                            __half* __restrict__ h, const int* __restrict__ dst,
                            int* __restrict__ deg) {
    int t = blockIdx.x * blockDim.x + threadIdx.x;
    if (t < NN * 8) {
        int n = t >> 3, j = t & 7;   // j: 8-float chunk
        const float4* e = (const float4*)(emb + (size_t)x[n] * DD) + j * 2;
        float4 v0 = e[0], v1 = e[1];
        uint4 o;
        __half2* op = (__half2*)&o;
        op[0] = __floats2half2_rn(v0.x, v0.y);
        op[1] = __floats2half2_rn(v0.z, v0.w);
        op[2] = __floats2half2_rn(v1.x, v1.y);
        op[3] = __floats2half2_rn(v1.z, v1.w);
        *(uint4*)(h + (size_t)n * DD + j * 8) = o;
    } else {
        int e = t - NN * 8;
        if (e < NE) atomicAdd(&deg[dst[e]], 1);
    }
}

// ---------- single-kernel decoupled-lookback exclusive scan ----------
__global__ __launch_bounds__(SCAN_B) void k_scan_lb(
    const int* __restrict__ deg, int* __restrict__ off,
    volatile int* agg, volatile int* inc) {
    __shared__ int wsum[32];
    __shared__ int stotal;
    __shared__ int sbase;
    int b = blockIdx.x, t = threadIdx.x, w = t >> 5, l = t & 31;
    int n = b * SCAN_B + t;
    int v = (n < NN) ? deg[n] : 0;
    int s = v;
    #pragma unroll
    for (int d = 1; d < 32; d <<= 1) {
        int x = __shfl_up_sync(0xffffffffu, s, d);
        if (l >= d) s += x;
    }
    if (l == 31) wsum[w] = s;
    __syncthreads();
    if (w == 0) {
        int x = wsum[l], y = x;
        #pragma unroll
        for (int d = 1; d < 32; d <<= 1) {
            int z = __shfl_up_sync(0xffffffffu, y, d);
            if (l >= d) y += z;
        }
        wsum[l] = y - x;            // exclusive warp base
        if (l == 31) stotal = y;    // block total
    }
    __syncthreads();

    if (w == 0) {
        if (l == 0) { agg[b] = stotal; __threadfence(); }
        __syncwarp();
        int excl = 0;
        int i = b - 1;
        while (i >= 0) {
            int idx = i - l;
            int vi = -1, ai = -1;
            if (idx >= 0) {
                while (true) {
                    vi = inc[idx];
                    if (vi >= 0) break;
                    ai = agg[idx];
                    if (ai >= 0) break;
                }
            }
            unsigned has_inc = __ballot_sync(0xffffffffu, idx >= 0 && vi >= 0);
            int cut = has_inc ? (__ffs(has_inc) - 1) : 32;
            int contrib = 0;
            if (idx >= 0) {
                if (l < cut) contrib = ai;        // lanes < cut exited with ai >= 0
                else if (l == cut) contrib = vi;  // inclusive prefix through idx
            }
            #pragma unroll
            for (int d = 16; d > 0; d >>= 1)
                contrib += __shfl_xor_sync(0xffffffffu, contrib, d);
            excl += contrib;
            if (cut < 32) break;
            i -= 32;
        }
        if (l == 0) {
            sbase = excl;
            inc[b] = excl + stotal;
            __threadfence();
        }
    }
    __syncthreads();
    if (n < NN) off[n] = sbase + wsum[w] + (s - v);   // exclusive
}

// ---------- CSR fill ----------
__global__ void k_fill(const int* __restrict__ src, const int* __restrict__ dst,
                       const int* __restrict__ off, int* __restrict__ cursor,
                       int* __restrict__ elist) {
    int e = blockIdx.x * blockDim.x + threadIdx.x;
    if (e >= NE) return;
    int d = dst[e];
    int p = atomicAdd(&cursor[d], 1);
    elist[off[d] + p] = src[e];
}

// ---------- mean aggregation: one warp per node, fp16 gather, fp32 accum ----------
__global__ __launch_bounds__(256) void k_aggmean(
    const __half* __restrict__ h, const int* __restrict__ elist,
    const int* __restrict__ off, const int* __restrict__ deg,
    __half* __restrict__ mean) {
    int w = (blockIdx.x * blockDim.x + threadIdx.x) >> 5;
    int lane = threadIdx.x & 31;
    if (w >= NN) return;
    int beg = off[w], dg = deg[w];
    float2 a0 = make_float2(0.f, 0.f), a1 = a0;
    int i = beg, end = beg + dg;
    for (; i + 1 < end; i += 2) {
        int s0 = elist[i], s1 = elist[i + 1];
        float2 v0 = __half22float2(((const __half2*)(h + (size_t)s0 * DD))[lane]);
        float2 v1 = __half22float2(((const __half2*)(h + (size_t)s1 * DD))[lane]);
        a0.x += v0.x; a0.y += v0.y;
        a1.x += v1.x; a1.y += v1.y;
    }
    if (i < end) {
        int s0 = elist[i];
        float2 v0 = __half22float2(((const __half2*)(h + (size_t)s0 * DD))[lane]);
        a0.x += v0.x; a0.y += v0.y;
    }
    float inv = 1.0f / (float)max(dg, 1);
    ((__half2*)(mean + (size_t)w * DD))[lane] =
        __floats2half2_rn((a0.x + a1.x) * inv, (a0.y + a1.y) * inv);
}

// ---------- tensor-core dual GEMM + bias + relu ----------
// out[n] = relu( mean[n] @ Wl^T + bl + h[n] @ Wr^T ), fp32 accumulate.
// POOL=false: store fp16 out. POOL=true: no store; pool fp32 relu'd values per graph.
#define ASTR 136   // halves per row (272B: 16B bank rotation, conflict-free ldmatrix)

__device__ __forceinline__ uint32_t smem_u32(const void* p) {
    uint32_t a;
    asm("{ .reg .u64 t; cvta.to.shared.u64 t, %1; cvt.u32.u64 %0, t; }" : "=r"(a) : "l"(p));
    return a;
}
__device__ __forceinline__ void ldm_x4(uint32_t& r0, uint32_t& r1, uint32_t& r2,
                                       uint32_t& r3, uint32_t addr) {
    asm volatile("ldmatrix.sync.aligned.m8n8.x4.shared.b16 {%0,%1,%2,%3}, [%4];"
                 : "=r"(r0), "=r"(r1), "=r"(r2), "=r"(r3) : "r"(addr));
}
__device__ __forceinline__ void mma16816(float* c, uint32_t a0, uint32_t a1,
                                         uint32_t a2, uint32_t a3,
                                         uint32_t b0, uint32_t b1) {
    asm volatile("mma.sync.aligned.m16n8k16.row.col.f32.f16.f16.f32 "
                 "{%0,%1,%2,%3}, {%4,%5,%6,%7}, {%8,%9}, {%0,%1,%2,%3};"
                 : "+f"(c[0]), "+f"(c[1]), "+f"(c[2]), "+f"(c[3])
                 : "r"(a0), "r"(a1), "r"(a2), "r"(a3), "r"(b0), "r"(b1));
}

template <bool POOL>
__global__ __launch_bounds__(256) void k_linear_t(
    const __half* __restrict__ mean, const __half* __restrict__ h,
    const float* __restrict__ Wl, const float* __restrict__ bl,
    const float* __restrict__ Wr, __half* __restrict__ out,
    const int* __restrict__ batch, float* __restrict__ pool,
    float* __restrict__ gcnt)
{
    extern __shared__ __half smem[];
    __half* sB = smem;                 // [64][ASTR]
    __half* sA = smem + 64 * ASTR;     // [128][ASTR]
    const int tid  = threadIdx.x;
    const int w    = tid >> 5;
    const int lane = tid & 31;
    const int n0   = blockIdx.x * 128;

    // Stage B: sB[d][k] = Wl[d][k] (k<64), Wr[d][k-64] (k>=64), fp16
    for (int i = tid; i < 64 * 64; i += 256) {
        int d = i >> 6, k = i & 63;
        sB[d * ASTR + k]      = __float2half(Wl[i]);
        sB[d * ASTR + 64 + k] = __float2half(Wr[i]);
    }

    // Stage A: straight fp16 16B copies. qq<8 -> mean chunk qq, else h chunk qq-8.
    for (int i = tid; i < 128 * 16; i += 256) {
        int m = i >> 4, qq = i & 15;
        int n = n0 + m;
        uint4 v = make_uint4(0u, 0u, 0u, 0u);
        if (n < NN) {
            const __half* srcp = (qq < 8)
                ? (mean + (size_t)n * DD + qq * 8)
                : (h    + (size_t)n * DD + (qq - 8) * 8);
            v = *(const uint4*)srcp;
        }
        *(uint4*)(sA + m * ASTR + qq * 8) = v;
    }

    // Accumulators: 8 n-frags (16x8 each) covering N=64; init with bias.
    float c[8][4];
    const int cb = (lane & 3) * 2;
    {
        #pragma unroll
        for (int nf = 0; nf < 8; nf++) {
            float b0 = bl[nf * 8 + cb];
            float b1 = bl[nf * 8 + cb + 1];
            c[nf][0] = b0; c[nf][1] = b1;
            c[nf][2] = b0; c[nf][3] = b1;
        }
    }
    __syncthreads();

    // ldmatrix lane addresses
    uint32_t sA_u = smem_u32(sA);
    uint32_t sB_u = smem_u32(sB);
    int a_row = w * 16 + (lane & 15);
    uint32_t a_addr = sA_u + (uint32_t)(a_row * ASTR + ((lane >> 4) << 3)) * 2;
    int b_row_base = (lane & 7) + ((lane >> 3) & 1) * 8;
    uint32_t b_col = ((lane >> 4) << 3);
    uint32_t b_addr0 = sB_u + (uint32_t)((b_row_base +  0) * ASTR + b_col) * 2;
    uint32_t b_addr1 = sB_u + (uint32_t)((b_row_base + 16) * ASTR + b_col) * 2;
    uint32_t b_addr2 = sB_u + (uint32_t)((b_row_base + 32) * ASTR + b_col) * 2;
    uint32_t b_addr3 = sB_u + (uint32_t)((b_row_base + 48) * ASTR + b_col) * 2;

    #pragma unroll
    for (int ks = 0; ks < 8; ks++) {
        uint32_t koff = ks * 32;   // 16 halves = 32 bytes per k-step
        uint32_t a0, a1, a2, a3;
        ldm_x4(a0, a1, a2, a3, a_addr + koff);
        uint32_t b0, b1, b2, b3;
        ldm_x4(b0, b1, b2, b3, b_addr0 + koff);
        mma16816(c[0], a0, a1, a2, a3, b0, b2);
        mma16816(c[1], a0, a1, a2, a3, b1, b3);
        ldm_x4(b0, b1, b2, b3, b_addr1 + koff);
        mma16816(c[2], a0, a1, a2, a3, b0, b2);
        mma16816(c[3], a0, a1, a2, a3, b1, b3);
        ldm_x4(b0, b1, b2, b3, b_addr2 + koff);
        mma16816(c[4], a0, a1, a2, a3, b0, b2);
        mma16816(c[5], a0, a1, a2, a3, b1, b3);
        ldm_x4(b0, b1, b2, b3, b_addr3 + koff);
        mma16816(c[6], a0, a1, a2, a3, b0, b2);
        mma16816(c[7], a0, a1, a2, a3, b1, b3);
    }

    int r0 = n0 + w * 16 + (lane >> 2);
    int r1 = r0 + 8;

    if (!POOL) {
        // Store fp16 with relu
        if (r0 < NN) {
            __half* o = out + (size_t)r0 * DD;
            #pragma unroll
            for (int nf = 0; nf < 8; nf++)
                *(__half2*)&o[nf * 8 + cb] =
                    __floats2half2_rn(fmaxf(c[nf][0], 0.f), fmaxf(c[nf][1], 0.f));
        }
        if (r1 < NN) {
            __half* o = out + (size_t)r1 * DD;
            #pragma unroll
            for (int nf = 0; nf < 8; nf++)
                *(__half2*)&o[nf * 8 + cb] =
                    __floats2half2_rn(fmaxf(c[nf][2], 0.f), fmaxf(c[nf][3], 0.f));
        }
    } else {
        // Pool relu'd fp32 values per graph (no h2 materialization)
        int g0 = (r0 < NN) ? batch[r0] : -1;
        int g1 = (r1 < NN) ? batch[r1] : -1;
        if (g0 >= 0 && g0 == g1) {
            float* p = pool + (size_t)g0 * DD;
            #pragma unroll
            for (int nf = 0; nf < 8; nf++) {
                float s0 = fmaxf(c[nf][0], 0.f) + fmaxf(c[nf][2], 0.f);
                float s1 = fmaxf(c[nf][1], 0.f) + fmaxf(c[nf][3], 0.f);
                red_v2(p + nf * 8 + cb, s0, s1);
            }
            if (cb == 0) atomicAdd(&gcnt[g0], 2.0f);
        } else {
            if (g0 >= 0) {
                float* p = pool + (size_t)g0 * DD;
                #pragma unroll
                for (int nf = 0; nf < 8; nf++)
                    red_v2(p + nf * 8 + cb, fmaxf(c[nf][0], 0.f), fmaxf(c[nf][1], 0.f));
                if (cb == 0) atomicAdd(&gcnt[g0], 1.0f);
            }
            if (g1 >= 0) {
                float* p = pool + (size_t)g1 * DD;
                #pragma unroll
                for (int nf = 0; nf < 8; nf++)
                    red_v2(p + nf * 8 + cb, fmaxf(c[nf][2], 0.f), fmaxf(c[nf][3], 0.f));
                if (cb == 0) atomicAdd(&gcnt[g1], 1.0f);
            }
        }
    }
}

// ---------- classifier ----------
__global__ void k_out(const float* __restrict__ pool, const float* __restrict__ gcnt,
                      const float* __restrict__ Wout, const float* __restrict__ bout,
                      float* __restrict__ out) {
    int t = blockIdx.x * blockDim.x + threadIdx.x;
    if (t >= NG * 2) return;
    int g = t >> 1, c = t & 1;
    float inv = 1.0f / fmaxf(gcnt[g], 1.0f);
    float acc = bout[c];
    const float* p = pool + (size_t)g * DD;
    const float* w = Wout + (size_t)c * DD;
    #pragma unroll
    for (int k = 0; k < DD; k++) acc += p[k] * inv * w[k];
    out[(size_t)g * 2 + c] = acc;
}

extern "C" void kernel_launch(void* const* d_in, const int* in_sizes, int n_in,
                              void* d_out, int out_size) {
    const int*   x     = (const int*)d_in[0];
    const int*   ei    = (const int*)d_in[1];
    const int*   src   = ei;          // edge_index[0]
    const int*   dst   = ei + NE;     // edge_index[1]
    const int*   batch = (const int*)d_in[2];
    const float* emb   = (const float*)d_in[3];
    const float* W1l   = (const float*)d_in[4];
    const float* b1l   = (const float*)d_in[5];
    const float* W1r   = (const float*)d_in[6];
    const float* W2l   = (const float*)d_in[7];
    const float* b2l   = (const float*)d_in[8];
    const float* W2r   = (const float*)d_in[9];
    const float* Wout  = (const float*)d_in[10];
    const float* bout  = (const float*)d_in[11];
    float* out = (float*)d_out;

    __half *h0, *h1, *mean16;
    float* poolcnt;
    int *degcur, *off, *elist, *scanstat;
    cudaGetSymbolAddress((void**)&h0,       g_h16_0);
    cudaGetSymbolAddress((void**)&h1,       g_h16_1);
    cudaGetSymbolAddress((void**)&mean16,   g_mean16);
    cudaGetSymbolAddress((void**)&poolcnt,  g_poolcnt);
    cudaGetSymbolAddress((void**)&degcur,   g_degcur);
    cudaGetSymbolAddress((void**)&off,      g_off);
    cudaGetSymbolAddress((void**)&elist,    g_elist);
    cudaGetSymbolAddress((void**)&scanstat, g_scanstat);
    int*   deg    = degcur;
    int*   cursor = degcur + NN;
    float* pool   = poolcnt;
    float* gcnt   = poolcnt + (size_t)NG * DD;
    int*   agg    = scanstat;
    int*   inc    = scanstat + SCAN_NB;

    const int SMEM_LIN = (64 * ASTR + 128 * ASTR) * 2;   // 52224 bytes
    cudaFuncSetAttribute(k_linear_t<false>, cudaFuncAttributeMaxDynamicSharedMemorySize, SMEM_LIN);
    cudaFuncSetAttribute(k_linear_t<true>,  cudaFuncAttributeMaxDynamicSharedMemorySize, SMEM_LIN);

    cudaMemsetAsync(degcur,   0,    2 * NN * sizeof(int));
    cudaMemsetAsync(scanstat, 0xFF, 2 * SCAN_NB * sizeof(int));
    cudaMemsetAsync(poolcnt,  0,    ((size_t)NG * DD + NG) * sizeof(float));

    const int T = 256;
    const int LIN_GRID = (NN + 127) / 128;   // 782

    // CSR build (reused by both layers)
    k_gatherdeg<<<(NN * 8 + NE + T - 1) / T, T>>>(x, emb, h0, dst, deg);
    k_scan_lb<<<SCAN_NB, SCAN_B>>>(deg, off, agg, inc);
    k_fill<<<(NE + T - 1) / T, T>>>(src, dst, off, cursor, elist);

    // Layer 1
    k_aggmean<<<(NN * 32 + T - 1) / T, T>>>(h0, elist, off, deg, mean16);
    k_linear_t<false><<<LIN_GRID, 256, SMEM_LIN>>>(mean16, h0, W1l, b1l, W1r, h1,
                                                   nullptr, nullptr, nullptr);

    // Layer 2 (pool fused into epilogue; no h2 materialization)
    k_aggmean<<<(NN * 32 + T - 1) / T, T>>>(h1, elist, off, deg, mean16);
    k_linear_t<true><<<LIN_GRID, 256, SMEM_LIN>>>(mean16, h1, W2l, b2l, W2r, nullptr,
                                                  batch, pool, gcnt);

    // Classify
    k_out<<<(NG * 2 + 127) / 128, 128>>>(pool, gcnt, Wout, bout, out);
}

// round 16
// speedup vs baseline: 2.2909x; 1.0166x over previous
#include <cuda_runtime.h>
#include <cuda_bf16.h>
#include <cuda_fp16.h>
#include <cstdint>

#define NN 100000
#define NE 1200000
#define NG 2048
#define DD 64
#define SCAN_B 1024
#define SCAN_NB 98   // 98*1024 = 100352 >= NN

// Scratch (allocation-free, __device__ globals). All h storage is fp16.
__device__ __align__(16) __half g_h16_0[(size_t)NN * DD];
__device__ __align__(16) __half g_h16_1[(size_t)NN * DD];
__device__ __align__(16) __half g_mean16[(size_t)NN * DD];
__device__ float g_poolcnt[(size_t)NG * DD + NG];   // pool | gcnt
__device__ int   g_degcur[2 * NN];                  // deg | cursor
__device__ int   g_off[NN];
__device__ int   g_elist[NE];
__device__ int   g_scanstat[2 * SCAN_NB];           // agg | inc (init 0xFF)

typedef unsigned long long u64;

__device__ __forceinline__ void red_v2(float* p, float a, float b) {
    asm volatile("red.global.add.v2.f32 [%0], {%1, %2};"
                 :: "l"(p), "f"(a), "f"(b) : "memory");
}
__device__ __forceinline__ u64 pk2(float lo, float hi) {
    u64 r;
    asm("mov.b64 %0, {%1, %2};" : "=l"(r) : "f"(lo), "f"(hi));
    return r;
}
__device__ __forceinline__ void upk2(float& lo, float& hi, u64 v) {
    asm("mov.b64 {%0, %1}, %2;" : "=f"(lo), "=f"(hi) : "l"(v));
}
__device__ __forceinline__ void add2(u64& acc, u64 v) {
    asm("add.rn.f32x2 %0, %0, %1;" : "+l"(acc) : "l"(v));
}

// ---------- fused: h0[n] = fp16(emb[x[n]])  AND  deg[dst[e]] += 1 ----------
__global__ void k_gatherdeg(const int* __restrict__ x, const float* __restrict__ emb,
                            __half* __restrict__ h, const int* __restrict__ dst,
                            int* __restrict__ deg) {
    int t = blockIdx.x * blockDim.x + threadIdx.x;
    if (t < NN * 8) {
        int n = t >> 3, j = t & 7;   // j: 8-float chunk
        const float4* e = (const float4*)(emb + (size_t)x[n] * DD) + j * 2;
        float4 v0 = e[0], v1 = e[1];
        uint4 o;
        __half2* op = (__half2*)&o;
        op[0] = __floats2half2_rn(v0.x, v0.y);
        op[1] = __floats2half2_rn(v0.z, v0.w);
        op[2] = __floats2half2_rn(v1.x, v1.y);
        op[3] = __floats2half2_rn(v1.z, v1.w);
        *(uint4*)(h + (size_t)n * DD + j * 8) = o;
    } else {
        int e = t - NN * 8;
        if (e < NE) atomicAdd(&deg[dst[e]], 1);
    }
}

// ---------- single-kernel decoupled-lookback exclusive scan ----------
__global__ __launch_bounds__(SCAN_B) void k_scan_lb(
    const int* __restrict__ deg, int* __restrict__ off,
    volatile int* agg, volatile int* inc) {
    __shared__ int wsum[32];
    __shared__ int stotal;
    __shared__ int sbase;
    int b = blockIdx.x, t = threadIdx.x, w = t >> 5, l = t & 31;
    int n = b * SCAN_B + t;
    int v = (n < NN) ? deg[n] : 0;
    int s = v;
    #pragma unroll
    for (int d = 1; d < 32; d <<= 1) {
        int x = __shfl_up_sync(0xffffffffu, s, d);
        if (l >= d) s += x;
    }
    if (l == 31) wsum[w] = s;
    __syncthreads();
    if (w == 0) {
        int x = wsum[l], y = x;
        #pragma unroll
        for (int d = 1; d < 32; d <<= 1) {
            int z = __shfl_up_sync(0xffffffffu, y, d);
            if (l >= d) y += z;
        }
        wsum[l] = y - x;            // exclusive warp base
        if (l == 31) stotal = y;    // block total
    }
    __syncthreads();

    if (w == 0) {
        if (l == 0) { agg[b] = stotal; __threadfence(); }
        __syncwarp();
        int excl = 0;
        int i = b - 1;
        while (i >= 0) {
            int idx = i - l;
            int vi = -1, ai = -1;
            if (idx >= 0) {
                while (true) {
                    vi = inc[idx];
                    if (vi >= 0) break;
                    ai = agg[idx];
                    if (ai >= 0) break;
                }
            }
            unsigned has_inc = __ballot_sync(0xffffffffu, idx >= 0 && vi >= 0);
            int cut = has_inc ? (__ffs(has_inc) - 1) : 32;
            int contrib = 0;
            if (idx >= 0) {
                if (l < cut) contrib = ai;
                else if (l == cut) contrib = vi;
            }
            #pragma unroll
            for (int d = 16; d > 0; d >>= 1)
                contrib += __shfl_xor_sync(0xffffffffu, contrib, d);
            excl += contrib;
            if (cut < 32) break;
            i -= 32;
        }
        if (l == 0) {
            sbase = excl;
            inc[b] = excl + stotal;
            __threadfence();
        }
    }
    __syncthreads();
    if (n < NN) off[n] = sbase + wsum[w] + (s - v);   // exclusive
}

// ---------- CSR fill ----------
__global__ void k_fill(const int* __restrict__ src, const int* __restrict__ dst,
                       const int* __restrict__ off, int* __restrict__ cursor,
                       int* __restrict__ elist) {
    int e = blockIdx.x * blockDim.x + threadIdx.x;
    if (e >= NE) return;
    int d = dst[e];
    int p = atomicAdd(&cursor[d], 1);
    elist[off[d] + p] = src[e];
}

// ---------- mean aggregation: one warp per node ----------
// fp16 gather; pairwise HADD2 on edge pairs; packed f32x2 accumulate.
__global__ __launch_bounds__(256) void k_aggmean(
    const __half* __restrict__ h, const int* __restrict__ elist,
    const int* __restrict__ off, const int* __restrict__ deg,
    __half* __restrict__ mean) {
    int w = (blockIdx.x * blockDim.x + threadIdx.x) >> 5;
    int lane = threadIdx.x & 31;
    if (w >= NN) return;
    int beg = off[w], dg = deg[w];
    u64 acc0 = pk2(0.f, 0.f), acc1 = acc0;
    int i = beg, end = beg + dg;
    for (; i + 3 < end; i += 4) {
        int s0 = elist[i],     s1 = elist[i + 1];
        int s2 = elist[i + 2], s3 = elist[i + 3];
        __half2 v0 = ((const __half2*)(h + (size_t)s0 * DD))[lane];
        __half2 v1 = ((const __half2*)(h + (size_t)s1 * DD))[lane];
        __half2 v2 = ((const __half2*)(h + (size_t)s2 * DD))[lane];
        __half2 v3 = ((const __half2*)(h + (size_t)s3 * DD))[lane];
        float2 p01 = __half22float2(__hadd2(v0, v1));
        float2 p23 = __half22float2(__hadd2(v2, v3));
        add2(acc0, pk2(p01.x, p01.y));
        add2(acc1, pk2(p23.x, p23.y));
    }
    if (i + 1 < end) {
        int s0 = elist[i], s1 = elist[i + 1];
        __half2 v0 = ((const __half2*)(h + (size_t)s0 * DD))[lane];
        __half2 v1 = ((const __half2*)(h + (size_t)s1 * DD))[lane];
        float2 p = __half22float2(__hadd2(v0, v1));
        add2(acc0, pk2(p.x, p.y));
        i += 2;
    }
    if (i < end) {
        int s0 = elist[i];
        float2 p = __half22float2(((const __half2*)(h + (size_t)s0 * DD))[lane]);
        add2(acc1, pk2(p.x, p.y));
    }
    add2(acc0, acc1);
    float ax, ay;
    upk2(ax, ay, acc0);
    float inv = 1.0f / (float)max(dg, 1);
    ((__half2*)(mean + (size_t)w * DD))[lane] = __floats2half2_rn(ax * inv, ay * inv);
}

// ---------- tensor-core dual GEMM + bias + relu ----------
// out[n] = relu( mean[n] @ Wl^T + bl + h[n] @ Wr^T ), fp32 accumulate.
// POOL=false: store fp16 out. POOL=true: no store; pool fp32 relu'd values per graph.
#define ASTR 136   // halves per row (272B: 16B bank rotation, conflict-free ldmatrix)

__device__ __forceinline__ uint32_t smem_u32(const void* p) {
    uint32_t a;
    asm("{ .reg .u64 t; cvta.to.shared.u64 t, %1; cvt.u32.u64 %0, t; }" : "=r"(a) : "l"(p));
    return a;
}
__device__ __forceinline__ void ldm_x4(uint32_t& r0, uint32_t& r1, uint32_t& r2,
                                       uint32_t& r3, uint32_t addr) {
    asm volatile("ldmatrix.sync.aligned.m8n8.x4.shared.b16 {%0,%1,%2,%3}, [%4];"
                 : "=r"(r0), "=r"(r1), "=r"(r2), "=r"(r3) : "r"(addr));
}
__device__ __forceinline__ void mma16816(float* c, uint32_t a0, uint32_t a1,
                                         uint32_t a2, uint32_t a3,
                                         uint32_t b0, uint32_t b1) {
    asm volatile("mma.sync.aligned.m16n8k16.row.col.f32.f16.f16.f32 "
                 "{%0,%1,%2,%3}, {%4,%5,%6,%7}, {%8,%9}, {%0,%1,%2,%3};"
                 : "+f"(c[0]), "+f"(c[1]), "+f"(c[2]), "+f"(c[3])
                 : "r"(a0), "r"(a1), "r"(a2), "r"(a3), "r"(b0), "r"(b1));
}

template <bool POOL>
__global__ __launch_bounds__(256) void k_linear_t(
    const __half* __restrict__ mean, const __half* __restrict__ h,
    const float* __restrict__ Wl, const float* __restrict__ bl,
    const float* __restrict__ Wr, __half* __restrict__ out,
    const int* __restrict__ batch, float* __restrict__ pool,
    float* __restrict__ gcnt)
{
    extern __shared__ __half smem[];
    __half* sB = smem;                 // [64][ASTR]
    __half* sA = smem + 64 * ASTR;     // [128][ASTR]
    const int tid  = threadIdx.x;
    const int w    = tid >> 5;
    const int lane = tid & 31;
    const int n0   = blockIdx.x * 128;

    // Stage B: sB[d][k] = Wl[d][k] (k<64), Wr[d][k-64] (k>=64), fp16
    for (int i = tid; i < 64 * 64; i += 256) {
        int d = i >> 6, k = i & 63;
        sB[d * ASTR + k]      = __float2half(Wl[i]);
        sB[d * ASTR + 64 + k] = __float2half(Wr[i]);
    }

    // Stage A: straight fp16 16B copies. qq<8 -> mean chunk qq, else h chunk qq-8.
    for (int i = tid; i < 128 * 16; i += 256) {
        int m = i >> 4, qq = i & 15;
        int n = n0 + m;
        uint4 v = make_uint4(0u, 0u, 0u, 0u);
        if (n < NN) {
            const __half* srcp = (qq < 8)
                ? (mean + (size_t)n * DD + qq * 8)
                : (h    + (size_t)n * DD + (qq - 8) * 8);
            v = *(const uint4*)srcp;
        }
        *(uint4*)(sA + m * ASTR + qq * 8) = v;
    }

    // Accumulators: 8 n-frags (16x8 each) covering N=64; init with bias.
    float c[8][4];
    const int cb = (lane & 3) * 2;
    {
        #pragma unroll
        for (int nf = 0; nf < 8; nf++) {
            float b0 = bl[nf * 8 + cb];
            float b1 = bl[nf * 8 + cb + 1];
            c[nf][0] = b0; c[nf][1] = b1;
            c[nf][2] = b0; c[nf][3] = b1;
        }
    }
    __syncthreads();

    // ldmatrix lane addresses
    uint32_t sA_u = smem_u32(sA);
    uint32_t sB_u = smem_u32(sB);
    int a_row = w * 16 + (lane & 15);
    uint32_t a_addr = sA_u + (uint32_t)(a_row * ASTR + ((lane >> 4) << 3)) * 2;
    int b_row_base = (lane & 7) + ((lane >> 3) & 1) * 8;
    uint32_t b_col = ((lane >> 4) << 3);
    uint32_t b_addr0 = sB_u + (uint32_t)((b_row_base +  0) * ASTR + b_col) * 2;
    uint32_t b_addr1 = sB_u + (uint32_t)((b_row_base + 16) * ASTR + b_col) * 2;
    uint32_t b_addr2 = sB_u + (uint32_t)((b_row_base + 32) * ASTR + b_col) * 2;
    uint32_t b_addr3 = sB_u + (uint32_t)((b_row_base + 48) * ASTR + b_col) * 2;

    #pragma unroll
    for (int ks = 0; ks < 8; ks++) {
        uint32_t koff = ks * 32;   // 16 halves = 32 bytes per k-step
        uint32_t a0, a1, a2, a3;
        ldm_x4(a0, a1, a2, a3, a_addr + koff);
        uint32_t b0, b1, b2, b3;
        ldm_x4(b0, b1, b2, b3, b_addr0 + koff);
        mma16816(c[0], a0, a1, a2, a3, b0, b2);
        mma16816(c[1], a0, a1, a2, a3, b1, b3);
        ldm_x4(b0, b1, b2, b3, b_addr1 + koff);
        mma16816(c[2], a0, a1, a2, a3, b0, b2);
        mma16816(c[3], a0, a1, a2, a3, b1, b3);
        ldm_x4(b0, b1, b2, b3, b_addr2 + koff);
        mma16816(c[4], a0, a1, a2, a3, b0, b2);
        mma16816(c[5], a0, a1, a2, a3, b1, b3);
        ldm_x4(b0, b1, b2, b3, b_addr3 + koff);
        mma16816(c[6], a0, a1, a2, a3, b0, b2);
        mma16816(c[7], a0, a1, a2, a3, b1, b3);
    }

    int r0 = n0 + w * 16 + (lane >> 2);
    int r1 = r0 + 8;

    if (!POOL) {
        if (r0 < NN) {
            __half* o = out + (size_t)r0 * DD;
            #pragma unroll
            for (int nf = 0; nf < 8; nf++)
                *(__half2*)&o[nf * 8 + cb] =
                    __floats2half2_rn(fmaxf(c[nf][0], 0.f), fmaxf(c[nf][1], 0.f));
        }
        if (r1 < NN) {
            __half* o = out + (size_t)r1 * DD;
            #pragma unroll
            for (int nf = 0; nf < 8; nf++)
                *(__half2*)&o[nf * 8 + cb] =
                    __floats2half2_rn(fmaxf(c[nf][2], 0.f), fmaxf(c[nf][3], 0.f));
        }
    } else {
        int g0 = (r0 < NN) ? batch[r0] : -1;
        int g1 = (r1 < NN) ? batch[r1] : -1;
        if (g0 >= 0 && g0 == g1) {
            float* p = pool + (size_t)g0 * DD;
            #pragma unroll
            for (int nf = 0; nf < 8; nf++) {
                float s0 = fmaxf(c[nf][0], 0.f) + fmaxf(c[nf][2], 0.f);
                float s1 = fmaxf(c[nf][1], 0.f) + fmaxf(c[nf][3], 0.f);
                red_v2(p + nf * 8 + cb, s0, s1);
            }
            if (cb == 0) atomicAdd(&gcnt[g0], 2.0f);
        } else {
            if (g0 >= 0) {
                float* p = pool + (size_t)g0 * DD;
                #pragma unroll
                for (int nf = 0; nf < 8; nf++)
                    red_v2(p + nf * 8 + cb, fmaxf(c[nf][0], 0.f), fmaxf(c[nf][1], 0.f));
                if (cb == 0) atomicAdd(&gcnt[g0], 1.0f);
            }
            if (g1 >= 0) {
                float* p = pool + (size_t)g1 * DD;
                #pragma unroll
                for (int nf = 0; nf < 8; nf++)
                    red_v2(p + nf * 8 + cb, fmaxf(c[nf][2], 0.f), fmaxf(c[nf][3], 0.f));
                if (cb == 0) atomicAdd(&gcnt[g1], 1.0f);
            }
        }
    }
}

// ---------- classifier ----------
__global__ void k_out(const float* __restrict__ pool, const float* __restrict__ gcnt,
                      const float* __restrict__ Wout, const float* __restrict__ bout,
                      float* __restrict__ out) {
    int t = blockIdx.x * blockDim.x + threadIdx.x;
    if (t >= NG * 2) return;
    int g = t >> 1, c = t & 1;
    float inv = 1.0f / fmaxf(gcnt[g], 1.0f);
    float acc = bout[c];
    const float* p = pool + (size_t)g * DD;
    const float* w = Wout + (size_t)c * DD;
    #pragma unroll
    for (int k = 0; k < DD; k++) acc += p[k] * inv * w[k];
    out[(size_t)g * 2 + c] = acc;
}

extern "C" void kernel_launch(void* const* d_in, const int* in_sizes, int n_in,
                              void* d_out, int out_size) {
    const int*   x     = (const int*)d_in[0];
    const int*   ei    = (const int*)d_in[1];
    const int*   src   = ei;          // edge_index[0]
    const int*   dst   = ei + NE;     // edge_index[1]
    const int*   batch = (const int*)d_in[2];
    const float* emb   = (const float*)d_in[3];
    const float* W1l   = (const float*)d_in[4];
    const float* b1l   = (const float*)d_in[5];
    const float* W1r   = (const float*)d_in[6];
    const float* W2l   = (const float*)d_in[7];
    const float* b2l   = (const float*)d_in[8];
    const float* W2r   = (const float*)d_in[9];
    const float* Wout  = (const float*)d_in[10];
    const float* bout  = (const float*)d_in[11];
    float* out = (float*)d_out;

    __half *h0, *h1, *mean16;
    float* poolcnt;
    int *degcur, *off, *elist, *scanstat;
    cudaGetSymbolAddress((void**)&h0,       g_h16_0);
    cudaGetSymbolAddress((void**)&h1,       g_h16_1);
    cudaGetSymbolAddress((void**)&mean16,   g_mean16);
    cudaGetSymbolAddress((void**)&poolcnt,  g_poolcnt);
    cudaGetSymbolAddress((void**)&degcur,   g_degcur);
    cudaGetSymbolAddress((void**)&off,      g_off);
    cudaGetSymbolAddress((void**)&elist,    g_elist);
    cudaGetSymbolAddress((void**)&scanstat, g_scanstat);
    int*   deg    = degcur;
    int*   cursor = degcur + NN;
    float* pool   = poolcnt;
    float* gcnt   = poolcnt + (size_t)NG * DD;
    int*   agg    = scanstat;
    int*   inc    = scanstat + SCAN_NB;

    const int SMEM_LIN = (64 * ASTR + 128 * ASTR) * 2;   // 52224 bytes
    cudaFuncSetAttribute(k_linear_t<false>, cudaFuncAttributeMaxDynamicSharedMemorySize, SMEM_LIN);
    cudaFuncSetAttribute(k_linear_t<true>,  cudaFuncAttributeMaxDynamicSharedMemorySize, SMEM_LIN);

    cudaMemsetAsync(degcur,   0,    2 * NN * sizeof(int));
    cudaMemsetAsync(scanstat, 0xFF, 2 * SCAN_NB * sizeof(int));
    cudaMemsetAsync(poolcnt,  0,    ((size_t)NG * DD + NG) * sizeof(float));

    const int T = 256;
    const int LIN_GRID = (NN + 127) / 128;   // 782

    // CSR build (reused by both layers)
    k_gatherdeg<<<(NN * 8 + NE + T - 1) / T, T>>>(x, emb, h0, dst, deg);
    k_scan_lb<<<SCAN_NB, SCAN_B>>>(deg, off, agg, inc);
    k_fill<<<(NE + T - 1) / T, T>>>(src, dst, off, cursor, elist);

    // Layer 1
    k_aggmean<<<(NN * 32 + T - 1) / T, T>>>(h0, elist, off, deg, mean16);
    k_linear_t<false><<<LIN_GRID, 256, SMEM_LIN>>>(mean16, h0, W1l, b1l, W1r, h1,
                                                   nullptr, nullptr, nullptr);

    // Layer 2 (pool fused into epilogue; no h2 materialization)
    k_aggmean<<<(NN * 32 + T - 1) / T, T>>>(h1, elist, off, deg, mean16);
    k_linear_t<true><<<LIN_GRID, 256, SMEM_LIN>>>(mean16, h1, W2l, b2l, W2r, nullptr,
                                                  batch, pool, gcnt);

    // Classify
    k_out<<<(NG * 2 + 127) / 128, 128>>>(pool, gcnt, Wout, bout, out);
}

// round 17
// speedup vs baseline: 2.3250x; 1.0149x over previous
#include <cuda_runtime.h>
#include <cuda_bf16.h>
#include <cuda_fp16.h>
#include <cstdint>

#define NN 100000
#define NE 1200000
#define NG 2048
#define DD 64
#define SCAN_B 1024
#define SCAN_NB 98   // 98*1024 = 100352 >= NN

// Scratch (allocation-free, __device__ globals). All h storage is fp16.
__device__ __align__(16) __half g_h16_0[(size_t)NN * DD];
__device__ __align__(16) __half g_h16_1[(size_t)NN * DD];
__device__ __align__(16) __half g_mean16[(size_t)NN * DD];
__device__ float g_poolcnt[(size_t)NG * DD + NG];   // pool | gcnt
__device__ int   g_deg[NN];
__device__ int   g_off[NN];
__device__ int   g_rank[NE];                        // edge rank within its dst
__device__ int   g_elist[NE];
__device__ int   g_scanstat[2 * SCAN_NB];           // agg | inc (init 0xFF)

typedef unsigned long long u64;

__device__ __forceinline__ void red_v2(float* p, float a, float b) {
    asm volatile("red.global.add.v2.f32 [%0], {%1, %2};"
                 :: "l"(p), "f"(a), "f"(b) : "memory");
}
__device__ __forceinline__ u64 pk2(float lo, float hi) {
    u64 r;
    asm("mov.b64 %0, {%1, %2};" : "=l"(r) : "f"(lo), "f"(hi));
    return r;
}
__device__ __forceinline__ void upk2(float& lo, float& hi, u64 v) {
    asm("mov.b64 {%0, %1}, %2;" : "=f"(lo), "=f"(hi) : "l"(v));
}
__device__ __forceinline__ void add2(u64& acc, u64 v) {
    asm("add.rn.f32x2 %0, %0, %1;" : "+l"(acc) : "l"(v));
}

// ---------- fused: h0[n] = fp16(emb[x[n]])  AND  rank[e] = deg[dst[e]]++ ----------
__global__ void k_gatherdeg(const int* __restrict__ x, const float* __restrict__ emb,
                            __half* __restrict__ h, const int* __restrict__ dst,
                            int* __restrict__ deg, int* __restrict__ rank) {
    int t = blockIdx.x * blockDim.x + threadIdx.x;
    if (t < NN * 8) {
        int n = t >> 3, j = t & 7;   // j: 8-float chunk
        const float4* e = (const float4*)(emb + (size_t)x[n] * DD) + j * 2;
        float4 v0 = e[0], v1 = e[1];
        uint4 o;
        __half2* op = (__half2*)&o;
        op[0] = __floats2half2_rn(v0.x, v0.y);
        op[1] = __floats2half2_rn(v0.z, v0.w);
        op[2] = __floats2half2_rn(v1.x, v1.y);
        op[3] = __floats2half2_rn(v1.z, v1.w);
        *(uint4*)(h + (size_t)n * DD + j * 8) = o;
    } else {
        int e = t - NN * 8;
        if (e < NE) rank[e] = atomicAdd(&deg[dst[e]], 1);
    }
}

// ---------- single-kernel decoupled-lookback exclusive scan ----------
__global__ __launch_bounds__(SCAN_B) void k_scan_lb(
    const int* __restrict__ deg, int* __restrict__ off,
    volatile int* agg, volatile int* inc) {
    __shared__ int wsum[32];
    __shared__ int stotal;
    __shared__ int sbase;
    int b = blockIdx.x, t = threadIdx.x, w = t >> 5, l = t & 31;
    int n = b * SCAN_B + t;
    int v = (n < NN) ? deg[n] : 0;
    int s = v;
    #pragma unroll
    for (int d = 1; d < 32; d <<= 1) {
        int x = __shfl_up_sync(0xffffffffu, s, d);
        if (l >= d) s += x;
    }
    if (l == 31) wsum[w] = s;
    __syncthreads();
    if (w == 0) {
        int x = wsum[l], y = x;
        #pragma unroll
        for (int d = 1; d < 32; d <<= 1) {
            int z = __shfl_up_sync(0xffffffffu, y, d);
            if (l >= d) y += z;
        }
        wsum[l] = y - x;            // exclusive warp base
        if (l == 31) stotal = y;    // block total
    }
    __syncthreads();

    if (w == 0) {
        if (l == 0) { agg[b] = stotal; __threadfence(); }
        __syncwarp();
        int excl = 0;
        int i = b - 1;
        while (i >= 0) {
            int idx = i - l;
            int vi = -1, ai = -1;
            if (idx >= 0) {
                while (true) {
                    vi = inc[idx];
                    if (vi >= 0) break;
                    ai = agg[idx];
                    if (ai >= 0) break;
                }
            }
            unsigned has_inc = __ballot_sync(0xffffffffu, idx >= 0 && vi >= 0);
            int cut = has_inc ? (__ffs(has_inc) - 1) : 32;
            int contrib = 0;
            if (idx >= 0) {
                if (l < cut) contrib = ai;
                else if (l == cut) contrib = vi;
            }
            #pragma unroll
            for (int d = 16; d > 0; d >>= 1)
                contrib += __shfl_xor_sync(0xffffffffu, contrib, d);
            excl += contrib;
            if (cut < 32) break;
            i -= 32;
        }
        if (l == 0) {
            sbase = excl;
            inc[b] = excl + stotal;
            __threadfence();
        }
    }
    __syncthreads();
    if (n < NN) off[n] = sbase + wsum[w] + (s - v);   // exclusive
}

// ---------- CSR fill, atomic-free (rank precomputed) ----------
__global__ void k_fill(const int* __restrict__ src, const int* __restrict__ dst,
                       const int* __restrict__ off, const int* __restrict__ rank,
                       int* __restrict__ elist) {
    int e = blockIdx.x * blockDim.x + threadIdx.x;
    if (e >= NE) return;
    elist[off[dst[e]] + rank[e]] = src[e];
}

// ---------- mean aggregation: one warp per node, MLP-8 ----------
// fp16 gather; pairwise HADD2 on edge pairs; packed f32x2 accumulate.
__global__ __launch_bounds__(256) void k_aggmean(
    const __half* __restrict__ h, const int* __restrict__ elist,
    const int* __restrict__ off, const int* __restrict__ deg,
    __half* __restrict__ mean) {
    int w = (blockIdx.x * blockDim.x + threadIdx.x) >> 5;
    int lane = threadIdx.x & 31;
    if (w >= NN) return;
    int beg = off[w], dg = deg[w];
    u64 acc0 = pk2(0.f, 0.f), acc1 = acc0, acc2 = acc0, acc3 = acc0;
    int i = beg, end = beg + dg;
    for (; i + 7 < end; i += 8) {
        int s0 = elist[i],     s1 = elist[i + 1];
        int s2 = elist[i + 2], s3 = elist[i + 3];
        int s4 = elist[i + 4], s5 = elist[i + 5];
        int s6 = elist[i + 6], s7 = elist[i + 7];
        __half2 v0 = ((const __half2*)(h + (size_t)s0 * DD))[lane];
        __half2 v1 = ((const __half2*)(h + (size_t)s1 * DD))[lane];
        __half2 v2 = ((const __half2*)(h + (size_t)s2 * DD))[lane];
        __half2 v3 = ((const __half2*)(h + (size_t)s3 * DD))[lane];
        __half2 v4 = ((const __half2*)(h + (size_t)s4 * DD))[lane];
        __half2 v5 = ((const __half2*)(h + (size_t)s5 * DD))[lane];
        __half2 v6 = ((const __half2*)(h + (size_t)s6 * DD))[lane];
        __half2 v7 = ((const __half2*)(h + (size_t)s7 * DD))[lane];
        float2 p01 = __half22float2(__hadd2(v0, v1));
        float2 p23 = __half22float2(__hadd2(v2, v3));
        float2 p45 = __half22float2(__hadd2(v4, v5));
        float2 p67 = __half22float2(__hadd2(v6, v7));
        add2(acc0, pk2(p01.x, p01.y));
        add2(acc1, pk2(p23.x, p23.y));
        add2(acc2, pk2(p45.x, p45.y));
        add2(acc3, pk2(p67.x, p67.y));
    }
    if (i + 3 < end) {
        int s0 = elist[i],     s1 = elist[i + 1];
        int s2 = elist[i + 2], s3 = elist[i + 3];
        __half2 v0 = ((const __half2*)(h + (size_t)s0 * DD))[lane];
        __half2 v1 = ((const __half2*)(h + (size_t)s1 * DD))[lane];
        __half2 v2 = ((const __half2*)(h + (size_t)s2 * DD))[lane];
        __half2 v3 = ((const __half2*)(h + (size_t)s3 * DD))[lane];
        float2 p01 = __half22float2(__hadd2(v0, v1));
        float2 p23 = __half22float2(__hadd2(v2, v3));
        add2(acc0, pk2(p01.x, p01.y));
        add2(acc1, pk2(p23.x, p23.y));
        i += 4;
    }
    if (i + 1 < end) {
        int s0 = elist[i], s1 = elist[i + 1];
        __half2 v0 = ((const __half2*)(h + (size_t)s0 * DD))[lane];
        __half2 v1 = ((const __half2*)(h + (size_t)s1 * DD))[lane];
        float2 p = __half22float2(__hadd2(v0, v1));
        add2(acc2, pk2(p.x, p.y));
        i += 2;
    }
    if (i < end) {
        int s0 = elist[i];
        float2 p = __half22float2(((const __half2*)(h + (size_t)s0 * DD))[lane]);
        add2(acc3, pk2(p.x, p.y));
    }
    add2(acc0, acc1);
    add2(acc2, acc3);
    add2(acc0, acc2);
    float ax, ay;
    upk2(ax, ay, acc0);
    float inv = 1.0f / (float)max(dg, 1);
    ((__half2*)(mean + (size_t)w * DD))[lane] = __floats2half2_rn(ax * inv, ay * inv);
}

// ---------- tensor-core dual GEMM + bias + relu ----------
// out[n] = relu( mean[n] @ Wl^T + bl + h[n] @ Wr^T ), fp32 accumulate.
// POOL=false: store fp16 out. POOL=true: no store; pool fp32 relu'd values per graph.
#define ASTR 136   // halves per row (272B: 16B bank rotation, conflict-free ldmatrix)

__device__ __forceinline__ uint32_t smem_u32(const void* p) {
    uint32_t a;
    asm("{ .reg .u64 t; cvta.to.shared.u64 t, %1; cvt.u32.u64 %0, t; }" : "=r"(a) : "l"(p));
    return a;
}
__device__ __forceinline__ void ldm_x4(uint32_t& r0, uint32_t& r1, uint32_t& r2,
                                       uint32_t& r3, uint32_t addr) {
    asm volatile("ldmatrix.sync.aligned.m8n8.x4.shared.b16 {%0,%1,%2,%3}, [%4];"
                 : "=r"(r0), "=r"(r1), "=r"(r2), "=r"(r3) : "r"(addr));
}
__device__ __forceinline__ void mma16816(float* c, uint32_t a0, uint32_t a1,
                                         uint32_t a2, uint32_t a3,
                                         uint32_t b0, uint32_t b1) {
    asm volatile("mma.sync.aligned.m16n8k16.row.col.f32.f16.f16.f32 "
                 "{%0,%1,%2,%3}, {%4,%5,%6,%7}, {%8,%9}, {%0,%1,%2,%3};"
                 : "+f"(c[0]), "+f"(c[1]), "+f"(c[2]), "+f"(c[3])
                 : "r"(a0), "r"(a1), "r"(a2), "r"(a3), "r"(b0), "r"(b1));
}

template <bool POOL>
__global__ __launch_bounds__(256) void k_linear_t(
    const __half* __restrict__ mean, const __half* __restrict__ h,
    const float* __restrict__ Wl, const float* __restrict__ bl,
    const float* __restrict__ Wr, __half* __restrict__ out,
    const int* __restrict__ batch, float* __restrict__ pool,
    float* __restrict__ gcnt)
{
    extern __shared__ __half smem[];
    __half* sB = smem;                 // [64][ASTR]
    __half* sA = smem + 64 * ASTR;     // [128][ASTR]
    const int tid  = threadIdx.x;
    const int w    = tid >> 5;
    const int lane = tid & 31;
    const int n0   = blockIdx.x * 128;

    // Stage B: sB[d][k] = Wl[d][k] (k<64), Wr[d][k-64] (k>=64), fp16
    for (int i = tid; i < 64 * 64; i += 256) {
        int d = i >> 6, k = i & 63;
        sB[d * ASTR + k]      = __float2half(Wl[i]);
        sB[d * ASTR + 64 + k] = __float2half(Wr[i]);
    }

    // Stage A: straight fp16 16B copies. qq<8 -> mean chunk qq, else h chunk qq-8.
    for (int i = tid; i < 128 * 16; i += 256) {
        int m = i >> 4, qq = i & 15;
        int n = n0 + m;
        uint4 v = make_uint4(0u, 0u, 0u, 0u);
        if (n < NN) {
            const __half* srcp = (qq < 8)
                ? (mean + (size_t)n * DD + qq * 8)
                : (h    + (size_t)n * DD + (qq - 8) * 8);
            v = *(const uint4*)srcp;
        }
        *(uint4*)(sA + m * ASTR + qq * 8) = v;
    }

    // Accumulators: 8 n-frags (16x8 each) covering N=64; init with bias.
    float c[8][4];
    const int cb = (lane & 3) * 2;
    {
        #pragma unroll
        for (int nf = 0; nf < 8; nf++) {
            float b0 = bl[nf * 8 + cb];
            float b1 = bl[nf * 8 + cb + 1];
            c[nf][0] = b0; c[nf][1] = b1;
            c[nf][2] = b0; c[nf][3] = b1;
        }
    }
    __syncthreads();

    // ldmatrix lane addresses
    uint32_t sA_u = smem_u32(sA);
    uint32_t sB_u = smem_u32(sB);
    int a_row = w * 16 + (lane & 15);
    uint32_t a_addr = sA_u + (uint32_t)(a_row * ASTR + ((lane >> 4) << 3)) * 2;
    int b_row_base = (lane & 7) + ((lane >> 3) & 1) * 8;
    uint32_t b_col = ((lane >> 4) << 3);
    uint32_t b_addr0 = sB_u + (uint32_t)((b_row_base +  0) * ASTR + b_col) * 2;
    uint32_t b_addr1 = sB_u + (uint32_t)((b_row_base + 16) * ASTR + b_col) * 2;
    uint32_t b_addr2 = sB_u + (uint32_t)((b_row_base + 32) * ASTR + b_col) * 2;
    uint32_t b_addr3 = sB_u + (uint32_t)((b_row_base + 48) * ASTR + b_col) * 2;

    #pragma unroll
    for (int ks = 0; ks < 8; ks++) {
        uint32_t koff = ks * 32;   // 16 halves = 32 bytes per k-step
        uint32_t a0, a1, a2, a3;
        ldm_x4(a0, a1, a2, a3, a_addr + koff);
        uint32_t b0, b1, b2, b3;
        ldm_x4(b0, b1, b2, b3, b_addr0 + koff);
        mma16816(c[0], a0, a1, a2, a3, b0, b2);
        mma16816(c[1], a0, a1, a2, a3, b1, b3);
        ldm_x4(b0, b1, b2, b3, b_addr1 + koff);
        mma16816(c[2], a0, a1, a2, a3, b0, b2);
        mma16816(c[3], a0, a1, a2, a3, b1, b3);
        ldm_x4(b0, b1, b2, b3, b_addr2 + koff);
        mma16816(c[4], a0, a1, a2, a3, b0, b2);
        mma16816(c[5], a0, a1, a2, a3, b1, b3);
        ldm_x4(b0, b1, b2, b3, b_addr3 + koff);
        mma16816(c[6], a0, a1, a2, a3, b0, b2);
        mma16816(c[7], a0, a1, a2, a3, b1, b3);
    }

    int r0 = n0 + w * 16 + (lane >> 2);
    int r1 = r0 + 8;

    if (!POOL) {
        if (r0 < NN) {
            __half* o = out + (size_t)r0 * DD;
            #pragma unroll
            for (int nf = 0; nf < 8; nf++)
                *(__half2*)&o[nf * 8 + cb] =
                    __floats2half2_rn(fmaxf(c[nf][0], 0.f), fmaxf(c[nf][1], 0.f));
        }
        if (r1 < NN) {
            __half* o = out + (size_t)r1 * DD;
            #pragma unroll
            for (int nf = 0; nf < 8; nf++)
                *(__half2*)&o[nf * 8 + cb] =
                    __floats2half2_rn(fmaxf(c[nf][2], 0.f), fmaxf(c[nf][3], 0.f));
        }
    } else {
        int g0 = (r0 < NN) ? batch[r0] : -1;
        int g1 = (r1 < NN) ? batch[r1] : -1;
        if (g0 >= 0 && g0 == g1) {
            float* p = pool + (size_t)g0 * DD;
            #pragma unroll
            for (int nf = 0; nf < 8; nf++) {
                float s0 = fmaxf(c[nf][0], 0.f) + fmaxf(c[nf][2], 0.f);
                float s1 = fmaxf(c[nf][1], 0.f) + fmaxf(c[nf][3], 0.f);
                red_v2(p + nf * 8 + cb, s0, s1);
            }
            if (cb == 0) atomicAdd(&gcnt[g0], 2.0f);
        } else {
            if (g0 >= 0) {
                float* p = pool + (size_t)g0 * DD;
                #pragma unroll
                for (int nf = 0; nf < 8; nf++)
                    red_v2(p + nf * 8 + cb, fmaxf(c[nf][0], 0.f), fmaxf(c[nf][1], 0.f));
                if (cb == 0) atomicAdd(&gcnt[g0], 1.0f);
            }
            if (g1 >= 0) {
                float* p = pool + (size_t)g1 * DD;
                #pragma unroll
                for (int nf = 0; nf < 8; nf++)
                    red_v2(p + nf * 8 + cb, fmaxf(c[nf][2], 0.f), fmaxf(c[nf][3], 0.f));
                if (cb == 0) atomicAdd(&gcnt[g1], 1.0f);
            }
        }
    }
}

// ---------- classifier ----------
__global__ void k_out(const float* __restrict__ pool, const float* __restrict__ gcnt,
                      const float* __restrict__ Wout, const float* __restrict__ bout,
                      float* __restrict__ out) {
    int t = blockIdx.x * blockDim.x + threadIdx.x;
    if (t >= NG * 2) return;
    int g = t >> 1, c = t & 1;
    float inv = 1.0f / fmaxf(gcnt[g], 1.0f);
    float acc = bout[c];
    const float* p = pool + (size_t)g * DD;
    const float* w = Wout + (size_t)c * DD;
    #pragma unroll
    for (int k = 0; k < DD; k++) acc += p[k] * inv * w[k];
    out[(size_t)g * 2 + c] = acc;
}

extern "C" void kernel_launch(void* const* d_in, const int* in_sizes, int n_in,
                              void* d_out, int out_size) {
    const int*   x     = (const int*)d_in[0];
    const int*   ei    = (const int*)d_in[1];
    const int*   src   = ei;          // edge_index[0]
    const int*   dst   = ei + NE;     // edge_index[1]
    const int*   batch = (const int*)d_in[2];
    const float* emb   = (const float*)d_in[3];
    const float* W1l   = (const float*)d_in[4];
    const float* b1l   = (const float*)d_in[5];
    const float* W1r   = (const float*)d_in[6];
    const float* W2l   = (const float*)d_in[7];
    const float* b2l   = (const float*)d_in[8];
    const float* W2r   = (const float*)d_in[9];
    const float* Wout  = (const float*)d_in[10];
    const float* bout  = (const float*)d_in[11];
    float* out = (float*)d_out;

    __half *h0, *h1, *mean16;
    float* poolcnt;
    int *deg, *off, *rank, *elist, *scanstat;
    cudaGetSymbolAddress((void**)&h0,       g_h16_0);
    cudaGetSymbolAddress((void**)&h1,       g_h16_1);
    cudaGetSymbolAddress((void**)&mean16,   g_mean16);
    cudaGetSymbolAddress((void**)&poolcnt,  g_poolcnt);
    cudaGetSymbolAddress((void**)&deg,      g_deg);
    cudaGetSymbolAddress((void**)&off,      g_off);
    cudaGetSymbolAddress((void**)&rank,     g_rank);
    cudaGetSymbolAddress((void**)&elist,    g_elist);
    cudaGetSymbolAddress((void**)&scanstat, g_scanstat);
    float* pool = poolcnt;
    float* gcnt = poolcnt + (size_t)NG * DD;
    int*   agg  = scanstat;
    int*   inc  = scanstat + SCAN_NB;

    const int SMEM_LIN = (64 * ASTR + 128 * ASTR) * 2;   // 52224 bytes
    cudaFuncSetAttribute(k_linear_t<false>, cudaFuncAttributeMaxDynamicSharedMemorySize, SMEM_LIN);
    cudaFuncSetAttribute(k_linear_t<true>,  cudaFuncAttributeMaxDynamicSharedMemorySize, SMEM_LIN);

    cudaMemsetAsync(deg,      0,    NN * sizeof(int));
    cudaMemsetAsync(scanstat, 0xFF, 2 * SCAN_NB * sizeof(int));
    cudaMemsetAsync(poolcnt,  0,    ((size_t)NG * DD + NG) * sizeof(float));

    const int T = 256;
    const int LIN_GRID = (NN + 127) / 128;   // 782

    // CSR build (reused by both layers)
    k_gatherdeg<<<(NN * 8 + NE + T - 1) / T, T>>>(x, emb, h0, dst, deg, rank);
    k_scan_lb<<<SCAN_NB, SCAN_B>>>(deg, off, agg, inc);
    k_fill<<<(NE + T - 1) / T, T>>>(src, dst, off, rank, elist);

    // Layer 1
    k_aggmean<<<(NN * 32 + T - 1) / T, T>>>(h0, elist, off, deg, mean16);
    k_linear_t<false><<<LIN_GRID, 256, SMEM_LIN>>>(mean16, h0, W1l, b1l, W1r, h1,
                                                   nullptr, nullptr, nullptr);

    // Layer 2 (pool fused into epilogue; no h2 materialization)
    k_aggmean<<<(NN * 32 + T - 1) / T, T>>>(h1, elist, off, deg, mean16);
    k_linear_t<true><<<LIN_GRID, 256, SMEM_LIN>>>(mean16, h1, W2l, b2l, W2r, nullptr,
                                                  batch, pool, gcnt);

    // Classify
    k_out<<<(NG * 2 + 127) / 128, 128>>>(pool, gcnt, Wout, bout, out);
}